// round 1
// baseline (speedup 1.0000x reference)
#include <cuda_runtime.h>
#include <cstddef>

#define HW    64
#define NPIX  4096
#define NG    8
#define NK    6
#define CF    256

// ---------------- scratch (device globals; no allocation anywhere) -------------
__device__ __align__(16) float g_inp[512 * NPIX];          // concat(gar, cond)  8MB
__device__ __align__(16) float g_h1 [NG * 128 * NPIX];     // 16MB
__device__ __align__(16) float g_h2 [NG *  64 * NPIX];     //  8MB
__device__ __align__(16) float g_h3 [NG *  32 * NPIX];     //  4MB
__device__ __align__(16) float g_oa [NG *  18 * NPIX];     //  2.25MB
__device__ __align__(16) float g_sx [NG * NK * NPIX];
__device__ __align__(16) float g_sy [NG * NK * NPIX];
__device__ __align__(16) float g_at [NG * NK * NPIX];
__device__ __align__(16) float g_hwc[NPIX * CF];           // gar_feat in HWC, 4MB

// ---------------- concat gar||cond into g_inp ----------------------------------
__global__ void concat_kernel(const float* __restrict__ gar,
                              const float* __restrict__ cond) {
    int i = blockIdx.x * blockDim.x + threadIdx.x;
    const int n = 256 * NPIX / 4;                 // float4 count per tensor
    float4* o = reinterpret_cast<float4*>(g_inp);
    if (i < n)           o[i]     = reinterpret_cast<const float4*>(gar )[i];
    else if (i < 2 * n)  o[i]     = reinterpret_cast<const float4*>(cond)[i - n];
}

// ---------------- transpose gar_feat [C][HW] -> [HW][C] -------------------------
__global__ void transpose_kernel(const float* __restrict__ in) {
    __shared__ float tile[32][33];
    int x = blockIdx.x * 32 + threadIdx.x;   // pixel
    int y = blockIdx.y * 32 + threadIdx.y;   // channel
    #pragma unroll
    for (int j = 0; j < 32; j += 8)
        tile[threadIdx.y + j][threadIdx.x] = in[(size_t)(y + j) * NPIX + x];
    __syncthreads();
    int x2 = blockIdx.y * 32 + threadIdx.x;  // channel
    int y2 = blockIdx.x * 32 + threadIdx.y;  // pixel
    #pragma unroll
    for (int j = 0; j < 32; j += 8)
        g_hwc[(size_t)(y2 + j) * CF + x2] = tile[threadIdx.x][threadIdx.y + j];
}

// ---------------- 3x3 SAME conv, implicit GEMM ---------------------------------
// Block: 256 threads. Tile: CT out-channels x 256 pixels (4 rows x 64 cols).
// Per-thread register tile: MO=CT/8 channels x 8 pixels.
template <int CIN, int COUT, int CT, bool RELU, bool GRP_IN>
__global__ __launch_bounds__(256, 2)
void conv3x3_k(const float* __restrict__ gin, const float* __restrict__ gw,
               const float* __restrict__ gb, float* __restrict__ gout) {
    constexpr int MO = CT / 8;
    __shared__ float s_in[8][6][66];
    __shared__ float s_w[8][9][CT + 1];           // +1 pad: conflict-free stores

    const int tid = threadIdx.x;
    const int g   = blockIdx.z;
    const int cob = blockIdx.y * CT;
    const int r0  = blockIdx.x * 4;

    const float* in = gin + (GRP_IN ? (size_t)g * CIN * NPIX : 0);
    const float* wp = gw + (size_t)g * COUT * CIN * 9;

    const int cg  = tid & 7;        // channel subgroup 0..7
    const int pg  = tid >> 3;       // pixel subgroup 0..31
    const int row = pg >> 3;        // 0..3
    const int c0  = (pg & 7) * 8;   // 0,8,...,56

    float acc[MO][8];
    #pragma unroll
    for (int m = 0; m < MO; m++) {
        int co = cob + cg * MO + m;
        float b = (co < COUT) ? gb[g * COUT + co] : 0.f;
        #pragma unroll
        for (int j = 0; j < 8; j++) acc[m][j] = b;
    }

    for (int cib = 0; cib < CIN; cib += 8) {
        __syncthreads();
        // stage input halo tile (8 ci x 6 rows x 66 cols)
        for (int idx = tid; idx < 8 * 6 * 66; idx += 256) {
            int ci = idx / 396; int rem = idx - ci * 396;
            int r  = rem / 66;  int cx  = rem - r * 66;
            int gy = r0 - 1 + r, gx = cx - 1;
            float v = 0.f;
            if (gy >= 0 && gy < HW && gx >= 0 && gx < HW)
                v = in[(size_t)(cib + ci) * NPIX + gy * HW + gx];
            s_in[ci][r][cx] = v;
        }
        // stage weights: contiguous global reads (tap,ci fast), padded smem
        for (int idx = tid; idx < 72 * CT; idx += 256) {
            int co = idx / 72; int rem = idx - co * 72;
            int ci = rem / 9;  int tap = rem - ci * 9;
            float v = 0.f;
            if (cob + co < COUT)
                v = wp[((size_t)(cob + co) * CIN + cib + ci) * 9 + tap];
            s_w[ci][tap][co] = v;
        }
        __syncthreads();

        for (int ci = 0; ci < 8; ci++) {
            float rv[3][10];
            #pragma unroll
            for (int dy = 0; dy < 3; dy++)
                #pragma unroll
                for (int t = 0; t < 10; t++)
                    rv[dy][t] = s_in[ci][row + dy][c0 + t];
            #pragma unroll
            for (int dy = 0; dy < 3; dy++)
                #pragma unroll
                for (int dx = 0; dx < 3; dx++) {
                    #pragma unroll
                    for (int m = 0; m < MO; m++) {
                        float w = s_w[ci][dy * 3 + dx][cg * MO + m];
                        #pragma unroll
                        for (int j = 0; j < 8; j++)
                            acc[m][j] += w * rv[dy][dx + j];
                    }
                }
        }
    }

    #pragma unroll
    for (int m = 0; m < MO; m++) {
        int co = cob + cg * MO + m;
        if ((COUT % CT != 0) && co >= COUT) continue;
        #pragma unroll
        for (int j = 0; j < 8; j++) {
            float v = acc[m][j];
            if (RELU) v = (v >= 0.f) ? v : 0.1f * v;
            gout[((size_t)g * COUT + co) * NPIX + (r0 + row) * HW + c0 + j] = v;
        }
    }
}

// ---------------- pass A: softmax attention + sample coords --------------------
__global__ void passA_kernel() {
    int idx = blockIdx.x * blockDim.x + threadIdx.x;   // [0, NK*NPIX)
    if (idx >= NK * NPIX) return;
    int p = idx & (NPIX - 1);
    int k = idx >> 12;
    int jx = p & 63, jy = p >> 6;

    float a[NG]; float mx = -1e30f;
    #pragma unroll
    for (int g = 0; g < NG; g++) {
        a[g] = g_oa[(size_t)(g * 18 + 12 + k) * NPIX + p];
        mx = fmaxf(mx, a[g]);
    }
    float s = 0.f;
    #pragma unroll
    for (int g = 0; g < NG; g++) { a[g] = __expf(a[g] - mx); s += a[g]; }
    float inv = 1.f / s;
    const float sc = 64.f / 63.f;
    #pragma unroll
    for (int g = 0; g < NG; g++) {
        int sidx = (g * NK + k) * NPIX + p;
        g_at[sidx] = a[g] * inv;
        float ox = g_oa[(size_t)(g * 18 + 2 * k    ) * NPIX + p];
        float oy = g_oa[(size_t)(g * 18 + 2 * k + 1) * NPIX + p];
        g_sx[sidx] = fminf(fmaxf((jx + ox) * sc - 0.5f, 0.f), 63.f);
        g_sy[sidx] = fminf(fmaxf((jy + oy) * sc - 0.5f, 0.f), 63.f);
    }
}

// ---------------- pass C: bilinear gather + attn/mask accumulate ----------------
// block (64,4): tx = x within row, ty -> 4-channel float4 chunk. grid (64 rows, 16)
__global__ void passC_kernel(const float* __restrict__ mask,
                             float* __restrict__ out) {
    int x = threadIdx.x;
    int p = blockIdx.x * HW + x;
    int c = blockIdx.y * 16 + threadIdx.y * 4;

    float4 acc = make_float4(0.f, 0.f, 0.f, 0.f);
    #pragma unroll
    for (int g = 0; g < NG; g++) {
        float4 part = make_float4(0.f, 0.f, 0.f, 0.f);
        #pragma unroll
        for (int k = 0; k < NK; k++) {
            int s = (g * NK + k) * NPIX + p;
            float sx = g_sx[s], sy = g_sy[s], a = g_at[s];
            float x0f = floorf(sx), y0f = floorf(sy);
            int x0 = (int)x0f, y0 = (int)y0f;
            float wx = sx - x0f, wy = sy - y0f;
            int x1 = min(x0 + 1, 63), y1 = min(y0 + 1, 63);
            const float4 v00 = *reinterpret_cast<const float4*>(&g_hwc[(size_t)(y0 * HW + x0) * CF + c]);
            const float4 v01 = *reinterpret_cast<const float4*>(&g_hwc[(size_t)(y0 * HW + x1) * CF + c]);
            const float4 v10 = *reinterpret_cast<const float4*>(&g_hwc[(size_t)(y1 * HW + x0) * CF + c]);
            const float4 v11 = *reinterpret_cast<const float4*>(&g_hwc[(size_t)(y1 * HW + x1) * CF + c]);
            float w00 = (1.f - wy) * (1.f - wx), w01 = (1.f - wy) * wx;
            float w10 = wy * (1.f - wx),         w11 = wy * wx;
            part.x += a * (w00 * v00.x + w01 * v01.x + w10 * v10.x + w11 * v11.x);
            part.y += a * (w00 * v00.y + w01 * v01.y + w10 * v10.y + w11 * v11.y);
            part.z += a * (w00 * v00.z + w01 * v01.z + w10 * v10.z + w11 * v11.z);
            part.w += a * (w00 * v00.w + w01 * v01.w + w10 * v10.w + w11 * v11.w);
        }
        const float4 mg = *reinterpret_cast<const float4*>(&mask[g * CF + c]);
        acc.x += mg.x * part.x; acc.y += mg.y * part.y;
        acc.z += mg.z * part.z; acc.w += mg.w * part.w;
    }
    out[(size_t)(c + 0) * NPIX + p] = acc.x;
    out[(size_t)(c + 1) * NPIX + p] = acc.y;
    out[(size_t)(c + 2) * NPIX + p] = acc.z;
    out[(size_t)(c + 3) * NPIX + p] = acc.w;
}

// ---------------- host launcher -------------------------------------------------
static float* sym_addr(const void* symbol) {
    void* p = nullptr;
    cudaGetSymbolAddress(&p, symbol);
    return reinterpret_cast<float*>(p);
}

extern "C" void kernel_launch(void* const* d_in, const int* in_sizes, int n_in,
                              void* d_out, int out_size) {
    const float* gar  = (const float*)d_in[0];
    const float* cond = (const float*)d_in[1];
    const float* mask = (const float*)d_in[2];
    const float* W1 = (const float*)d_in[3];
    const float* b1 = (const float*)d_in[4];
    const float* W2 = (const float*)d_in[5];
    const float* b2 = (const float*)d_in[6];
    const float* W3 = (const float*)d_in[7];
    const float* b3 = (const float*)d_in[8];
    const float* W4 = (const float*)d_in[9];
    const float* b4 = (const float*)d_in[10];
    float* out = (float*)d_out;

    float* p_inp = sym_addr(g_inp);
    float* p_h1  = sym_addr(g_h1);
    float* p_h2  = sym_addr(g_h2);
    float* p_h3  = sym_addr(g_h3);
    float* p_oa  = sym_addr(g_oa);

    concat_kernel<<<2048, 256>>>(gar, cond);
    transpose_kernel<<<dim3(NPIX / 32, CF / 32), dim3(32, 8)>>>(gar);

    conv3x3_k<512, 128, 64, true,  false><<<dim3(16, 2, NG), 256>>>(p_inp, W1, b1, p_h1);
    conv3x3_k<128,  64, 64, true,  true ><<<dim3(16, 1, NG), 256>>>(p_h1,  W2, b2, p_h2);
    conv3x3_k< 64,  32, 32, true,  true ><<<dim3(16, 1, NG), 256>>>(p_h2,  W3, b3, p_h3);
    conv3x3_k< 32,  18, 32, false, true ><<<dim3(16, 1, NG), 256>>>(p_h3,  W4, b4, p_oa);

    passA_kernel<<<(NK * NPIX + 255) / 256, 256>>>();
    passC_kernel<<<dim3(HW, 16), dim3(64, 4)>>>(mask, out);
}

// round 7
// speedup vs baseline: 2.9597x; 2.9597x over previous
#include <cuda_runtime.h>
#include <cstdint>
#include <cstddef>

#define HW    64
#define NPIX  4096
#define NG    8
#define NK    6

// ---------------- scratch (device globals; no allocation anywhere) -------------
__device__ __align__(1024) float g_hwcin[NPIX * 512];          // concat input, HWC
__device__ __align__(1024) float g_hwc1 [NG * NPIX * 128];
__device__ __align__(1024) float g_hwc2 [NG * NPIX *  64];
__device__ __align__(1024) float g_hwc3 [NG * NPIX *  32];
__device__ __align__(1024) float g_oa   [NG * 18 * NPIX];      // conv4 out NCHW
__device__ __align__(16)   float g_sx [NG * NK * NPIX];
__device__ __align__(16)   float g_sy [NG * NK * NPIX];
__device__ __align__(16)   float g_at [NG * NK * NPIX];
__device__ __align__(1024) float g_wr1[NG * 9 * 512 * 128];    // tf32 weights [g][tap][ci][cop]
__device__ __align__(1024) float g_wr2[NG * 9 * 128 *  64];
__device__ __align__(1024) float g_wr3[NG * 9 *  64 *  32];
__device__ __align__(1024) float g_wr4[NG * 9 *  32 *  24];

__device__ __forceinline__ uint32_t cvt_tf32(float f) {
    uint32_t u;
    asm("cvt.rna.tf32.f32 %0, %1;" : "=r"(u) : "f"(f));
    return u;
}

// ---------------- weight reorder: W[g][co][ci][3][3] -> Wr[g][tap][ci][COP] ------
template <int CI, int COUT, int COP>
__global__ void w_reorder(const float* __restrict__ w, float* __restrict__ wr) {
    const int total = NG * 9 * CI * COP;
    int i = blockIdx.x * blockDim.x + threadIdx.x;
    if (i >= total) return;
    int co  = i % COP;       int t = i / COP;
    int ci  = t % CI;        t /= CI;
    int tap = t % 9;         int g = t / 9;
    float v = 0.f;
    if (co < COUT) v = w[(((size_t)g * COUT + co) * CI + ci) * 9 + tap];
    reinterpret_cast<uint32_t*>(wr)[i] = cvt_tf32(v);
}

// ---------------- concat+transpose: [C][HW] x2 -> hwcin[p][512] ------------------
__global__ void hwc_concat_kernel(const float* __restrict__ gar,
                                  const float* __restrict__ cond) {
    __shared__ float t[32][33];
    int p  = blockIdx.x * 32 + threadIdx.x;
    int c0 = blockIdx.y * 32;
    const float* src = (c0 < 256) ? gar + (size_t)c0 * NPIX
                                  : cond + (size_t)(c0 - 256) * NPIX;
    #pragma unroll
    for (int j = 0; j < 32; j += 8)
        t[threadIdx.y + j][threadIdx.x] = src[(size_t)(threadIdx.y + j) * NPIX + p];
    __syncthreads();
    int p2 = blockIdx.x * 32 + threadIdx.y;
    int c  = c0 + threadIdx.x;
    #pragma unroll
    for (int j = 0; j < 32; j += 8)
        g_hwcin[(size_t)(p2 + j) * 512 + c] = t[threadIdx.x][threadIdx.y + j];
}

// ---------------- tf32 mma.sync implicit-GEMM 3x3 conv ---------------------------
// CTA: 128 px (2 image rows) x COTILE co. Halo tile staged once per 32-ci chunk;
// all 9 taps read shifted windows from it. B double-buffered + reg-prefetched.
template <int CI, int COUT, int COP, int COTILE, int WPX,
          bool RELU, bool OUT_HWC, bool GRP_IN>
__global__ __launch_bounds__(256, 2)
void gemm_conv(const float* __restrict__ hwc, const float* __restrict__ wr,
               const float* __restrict__ bias, float* __restrict__ outp) {
    constexpr int WCO    = 8 / WPX;
    constexpr int WarpPx = 128 / WPX;
    constexpr int MT     = WarpPx / 16;
    constexpr int WarpCo = COTILE / WCO;
    constexpr int NT     = WarpCo / 8;
    constexpr int BS     = (COTILE <= 32) ? 40 : 72;   // B smem row stride (floats)
    constexpr int NCC    = CI / 32;
    constexpr int NTOT   = NCC * 9;
    constexpr int AW     = 264 * 36;                   // halo tile words
    constexpr int BW     = 32 * BS;
    constexpr int NB4    = 32 * COTILE / 4;            // float4s per B stage
    constexpr int NBT    = (NB4 + 255) / 256;

    extern __shared__ float sm[];
    float* sA = sm;              // [2][AW]
    float* sB = sm + 2 * AW;     // [2][BW]

    const int tid = threadIdx.x, lane = tid & 31, wid = tid >> 5;
    const int g   = blockIdx.z;
    const int cob = blockIdx.y * COTILE;
    const int r0  = blockIdx.x * 2;
    const int p0  = blockIdx.x * 128;

    const float* inb = GRP_IN ? hwc + (size_t)g * NPIX * CI : hwc;
    const float* wb  = wr + (size_t)g * 9 * CI * COP;

    const int wco = wid % WCO, wpx = wid / WCO;
    const int r4  = lane >> 2, l4 = lane & 3;

    // ---- prologue: stage halo chunk 0 + B iter 0 ----
    for (int it = tid; it < 264 * 8; it += 256) {
        int pos = it >> 3, cf = it & 7;
        int hr = pos / 66, hc = pos - hr * 66;
        int y = r0 - 1 + hr, x = hc - 1;
        float4 v = make_float4(0.f, 0.f, 0.f, 0.f);
        if ((unsigned)y < 64u && (unsigned)x < 64u)
            v = *(const float4*)(inb + (size_t)(y * HW + x) * CI + cf * 4);
        uint32_t* d = (uint32_t*)(sA + pos * 36 + cf * 4);
        d[0] = cvt_tf32(v.x); d[1] = cvt_tf32(v.y);
        d[2] = cvt_tf32(v.z); d[3] = cvt_tf32(v.w);
    }
    #pragma unroll
    for (int t = 0; t < NBT; t++) {
        int it = tid + t * 256;
        if (it < NB4) {
            int ci = it / (COTILE / 4), cf = it - ci * (COTILE / 4);
            float4 v = *(const float4*)(wb + (size_t)ci * COP + cob + cf * 4);
            *(float4*)(sB + ci * BS + cf * 4) = v;
        }
    }
    __syncthreads();

    float acc[MT][NT][4];
    #pragma unroll
    for (int mt = 0; mt < MT; mt++)
        #pragma unroll
        for (int nt = 0; nt < NT; nt++)
            #pragma unroll
            for (int q = 0; q < 4; q++) acc[mt][nt][q] = 0.f;

    for (int c = 0; c < NTOT; c++) {
        const int cc = c / 9, tap = c - cc * 9;
        const int c1 = c + 1;

        // -- prefetch B(c+1) into regs --
        float4 brg[NBT];
        if (c1 < NTOT) {
            int cc2 = c1 / 9, tap2 = c1 - cc2 * 9;
            const float* bsrc = wb + ((size_t)tap2 * CI + cc2 * 32) * COP + cob;
            #pragma unroll
            for (int t = 0; t < NBT; t++) {
                int it = tid + t * 256;
                if (it < NB4) {
                    int ci = it / (COTILE / 4), cf = it - ci * (COTILE / 4);
                    brg[t] = *(const float4*)(bsrc + (size_t)ci * COP + cf * 4);
                }
            }
        }
        // -- prefetch A slice 'tap' of chunk cc+1 (30 pos x 8 cf = 240 items) --
        float4 arg = make_float4(0.f, 0.f, 0.f, 0.f);
        int apos = -1, acf = 0;
        if (cc + 1 < NCC && tid < 240) {
            int pos = tap * 30 + (tid >> 3);
            if (pos < 264) {
                apos = pos; acf = tid & 7;
                int hr = pos / 66, hc = pos - hr * 66;
                int y = r0 - 1 + hr, x = hc - 1;
                if ((unsigned)y < 64u && (unsigned)x < 64u)
                    arg = *(const float4*)(inb + (size_t)(y * HW + x) * CI
                                           + (cc + 1) * 32 + acf * 4);
            }
        }

        // -- compute current (cc, tap) --
        const uint32_t* uA = (const uint32_t*)(sA + (cc & 1) * AW);
        const uint32_t* uB = (const uint32_t*)(sB + (c  & 1) * BW);
        const int dy = tap / 3, dx = tap - dy * 3;
        const int dtap = (dy * 66 + dx) * 36;
        int abase[MT], bbase[NT];
        #pragma unroll
        for (int mt = 0; mt < MT; mt++) {
            int pb = wpx * WarpPx + mt * 16;
            abase[mt] = dtap + ((pb >> 6) * 66 + (pb & 63) + r4) * 36 + l4;
        }
        #pragma unroll
        for (int nt = 0; nt < NT; nt++)
            bbase[nt] = l4 * BS + wco * WarpCo + nt * 8 + r4;

        #pragma unroll
        for (int ks = 0; ks < 4; ks++) {
            uint32_t af[MT][4], bf[NT][2];
            #pragma unroll
            for (int mt = 0; mt < MT; mt++) {
                int a0 = abase[mt] + ks * 8;
                af[mt][0] = uA[a0];
                af[mt][1] = uA[a0 + 8 * 36];
                af[mt][2] = uA[a0 + 4];
                af[mt][3] = uA[a0 + 8 * 36 + 4];
            }
            #pragma unroll
            for (int nt = 0; nt < NT; nt++) {
                int b0 = bbase[nt] + ks * 8 * BS;
                bf[nt][0] = uB[b0];
                bf[nt][1] = uB[b0 + 4 * BS];
            }
            #pragma unroll
            for (int mt = 0; mt < MT; mt++)
                #pragma unroll
                for (int nt = 0; nt < NT; nt++)
                    asm volatile(
                        "mma.sync.aligned.m16n8k8.row.col.f32.tf32.tf32.f32 "
                        "{%0,%1,%2,%3}, {%4,%5,%6,%7}, {%8,%9}, {%0,%1,%2,%3};"
                        : "+f"(acc[mt][nt][0]), "+f"(acc[mt][nt][1]),
                          "+f"(acc[mt][nt][2]), "+f"(acc[mt][nt][3])
                        : "r"(af[mt][0]), "r"(af[mt][1]), "r"(af[mt][2]), "r"(af[mt][3]),
                          "r"(bf[nt][0]), "r"(bf[nt][1]));
        }

        // -- commit prefetched stages --
        if (c1 < NTOT) {
            float* dB = sB + (c1 & 1) * BW;
            #pragma unroll
            for (int t = 0; t < NBT; t++) {
                int it = tid + t * 256;
                if (it < NB4) {
                    int ci = it / (COTILE / 4), cf = it - ci * (COTILE / 4);
                    *(float4*)(dB + ci * BS + cf * 4) = brg[t];
                }
            }
        }
        if (apos >= 0) {
            uint32_t* d = (uint32_t*)(sA + ((cc + 1) & 1) * AW + apos * 36 + acf * 4);
            d[0] = cvt_tf32(arg.x); d[1] = cvt_tf32(arg.y);
            d[2] = cvt_tf32(arg.z); d[3] = cvt_tf32(arg.w);
        }
        __syncthreads();
    }

    // ---- epilogue: bias + leaky-ReLU + store ----
    #pragma unroll
    for (int mt = 0; mt < MT; mt++) {
        int pxl = wpx * WarpPx + mt * 16 + r4;       // local px (row r4)
        #pragma unroll
        for (int nt = 0; nt < NT; nt++) {
            int co = cob + wco * WarpCo + nt * 8 + 2 * l4;
            float v0 = acc[mt][nt][0], v1 = acc[mt][nt][1];
            float v2 = acc[mt][nt][2], v3 = acc[mt][nt][3];
            if (OUT_HWC) {
                float b0 = bias[g * COUT + co], b1 = bias[g * COUT + co + 1];
                v0 += b0; v1 += b1; v2 += b0; v3 += b1;
                if (RELU) {
                    v0 = (v0 >= 0.f) ? v0 : 0.1f * v0;
                    v1 = (v1 >= 0.f) ? v1 : 0.1f * v1;
                    v2 = (v2 >= 0.f) ? v2 : 0.1f * v2;
                    v3 = (v3 >= 0.f) ? v3 : 0.1f * v3;
                }
                float* ob = outp + (size_t)g * NPIX * COUT;
                *(float2*)(ob + (size_t)(p0 + pxl) * COUT + co)     = make_float2(v0, v1);
                *(float2*)(ob + (size_t)(p0 + pxl + 8) * COUT + co) = make_float2(v2, v3);
            } else {
                #pragma unroll
                for (int s = 0; s < 2; s++) {
                    int c2 = co + s;
                    if (c2 < COUT) {
                        float bv = bias[g * COUT + c2];
                        float va = (s ? v1 : v0) + bv;
                        float vb = (s ? v3 : v2) + bv;
                        if (RELU) {
                            va = (va >= 0.f) ? va : 0.1f * va;
                            vb = (vb >= 0.f) ? vb : 0.1f * vb;
                        }
                        float* ob = outp + ((size_t)g * COUT + c2) * NPIX + p0;
                        ob[pxl]     = va;
                        ob[pxl + 8] = vb;
                    }
                }
            }
        }
    }
}

// ---------------- pass A: softmax attention + sample coords --------------------
__global__ void passA_kernel() {
    int idx = blockIdx.x * blockDim.x + threadIdx.x;
    if (idx >= NK * NPIX) return;
    int p = idx & (NPIX - 1);
    int k = idx >> 12;
    int jx = p & 63, jy = p >> 6;

    float a[NG]; float mx = -1e30f;
    #pragma unroll
    for (int g = 0; g < NG; g++) {
        a[g] = g_oa[(size_t)(g * 18 + 12 + k) * NPIX + p];
        mx = fmaxf(mx, a[g]);
    }
    float s = 0.f;
    #pragma unroll
    for (int g = 0; g < NG; g++) { a[g] = __expf(a[g] - mx); s += a[g]; }
    float inv = 1.f / s;
    const float sc = 64.f / 63.f;
    #pragma unroll
    for (int g = 0; g < NG; g++) {
        int sidx = (g * NK + k) * NPIX + p;
        g_at[sidx] = a[g] * inv;
        float ox = g_oa[(size_t)(g * 18 + 2 * k    ) * NPIX + p];
        float oy = g_oa[(size_t)(g * 18 + 2 * k + 1) * NPIX + p];
        g_sx[sidx] = fminf(fmaxf((jx + ox) * sc - 0.5f, 0.f), 63.f);
        g_sy[sidx] = fminf(fmaxf((jy + oy) * sc - 0.5f, 0.f), 63.f);
    }
}

// ---------------- pass C: bilinear gather + attn/mask accumulate ----------------
__global__ void passC_kernel(const float* __restrict__ mask,
                             float* __restrict__ out) {
    int x = threadIdx.x;
    int p = blockIdx.x * HW + x;
    int c = blockIdx.y * 16 + threadIdx.y * 4;

    float4 acc = make_float4(0.f, 0.f, 0.f, 0.f);
    #pragma unroll
    for (int g = 0; g < NG; g++) {
        float4 part = make_float4(0.f, 0.f, 0.f, 0.f);
        #pragma unroll
        for (int k = 0; k < NK; k++) {
            int s = (g * NK + k) * NPIX + p;
            float sx = g_sx[s], sy = g_sy[s], a = g_at[s];
            float x0f = floorf(sx), y0f = floorf(sy);
            int x0 = (int)x0f, y0 = (int)y0f;
            float wx = sx - x0f, wy = sy - y0f;
            int x1 = min(x0 + 1, 63), y1 = min(y0 + 1, 63);
            const float4 v00 = *reinterpret_cast<const float4*>(&g_hwcin[(size_t)(y0 * HW + x0) * 512 + c]);
            const float4 v01 = *reinterpret_cast<const float4*>(&g_hwcin[(size_t)(y0 * HW + x1) * 512 + c]);
            const float4 v10 = *reinterpret_cast<const float4*>(&g_hwcin[(size_t)(y1 * HW + x0) * 512 + c]);
            const float4 v11 = *reinterpret_cast<const float4*>(&g_hwcin[(size_t)(y1 * HW + x1) * 512 + c]);
            float w00 = (1.f - wy) * (1.f - wx), w01 = (1.f - wy) * wx;
            float w10 = wy * (1.f - wx),         w11 = wy * wx;
            part.x += a * (w00 * v00.x + w01 * v01.x + w10 * v10.x + w11 * v11.x);
            part.y += a * (w00 * v00.y + w01 * v01.y + w10 * v10.y + w11 * v11.y);
            part.z += a * (w00 * v00.z + w01 * v01.z + w10 * v10.z + w11 * v11.z);
            part.w += a * (w00 * v00.w + w01 * v01.w + w10 * v10.w + w11 * v11.w);
        }
        const float4 mg = *reinterpret_cast<const float4*>(&mask[g * 256 + c]);
        acc.x += mg.x * part.x; acc.y += mg.y * part.y;
        acc.z += mg.z * part.z; acc.w += mg.w * part.w;
    }
    out[(size_t)(c + 0) * NPIX + p] = acc.x;
    out[(size_t)(c + 1) * NPIX + p] = acc.y;
    out[(size_t)(c + 2) * NPIX + p] = acc.z;
    out[(size_t)(c + 3) * NPIX + p] = acc.w;
}

// ---------------- host launcher -------------------------------------------------
static float* sym_addr(const void* symbol) {
    void* p = nullptr;
    cudaGetSymbolAddress(&p, symbol);
    return reinterpret_cast<float*>(p);
}

static constexpr int smem_bytes(int cotile) {
    int bs = (cotile <= 32) ? 40 : 72;
    return (2 * 264 * 36 + 2 * 32 * bs) * 4;
}

extern "C" void kernel_launch(void* const* d_in, const int* in_sizes, int n_in,
                              void* d_out, int out_size) {
    const float* gar  = (const float*)d_in[0];
    const float* cond = (const float*)d_in[1];
    const float* mask = (const float*)d_in[2];
    const float* W1 = (const float*)d_in[3];
    const float* b1 = (const float*)d_in[4];
    const float* W2 = (const float*)d_in[5];
    const float* b2 = (const float*)d_in[6];
    const float* W3 = (const float*)d_in[7];
    const float* b3 = (const float*)d_in[8];
    const float* W4 = (const float*)d_in[9];
    const float* b4 = (const float*)d_in[10];
    float* out = (float*)d_out;

    float* p_hwcin = sym_addr(g_hwcin);
    float* p_hwc1  = sym_addr(g_hwc1);
    float* p_hwc2  = sym_addr(g_hwc2);
    float* p_hwc3  = sym_addr(g_hwc3);
    float* p_oa    = sym_addr(g_oa);
    float* p_wr1   = sym_addr(g_wr1);
    float* p_wr2   = sym_addr(g_wr2);
    float* p_wr3   = sym_addr(g_wr3);
    float* p_wr4   = sym_addr(g_wr4);

    auto k1 = gemm_conv<512, 128, 128, 64, 4, true,  true,  false>;
    auto k2 = gemm_conv<128,  64,  64, 64, 4, true,  true,  true >;
    auto k3 = gemm_conv< 64,  32,  32, 32, 4, true,  true,  true >;
    auto k4 = gemm_conv< 32,  18,  24, 24, 8, false, false, true >;
    cudaFuncSetAttribute(k1, cudaFuncAttributeMaxDynamicSharedMemorySize, smem_bytes(64));
    cudaFuncSetAttribute(k2, cudaFuncAttributeMaxDynamicSharedMemorySize, smem_bytes(64));
    cudaFuncSetAttribute(k3, cudaFuncAttributeMaxDynamicSharedMemorySize, smem_bytes(32));
    cudaFuncSetAttribute(k4, cudaFuncAttributeMaxDynamicSharedMemorySize, smem_bytes(24));

    const int n1 = NG * 9 * 512 * 128;
    const int n2 = NG * 9 * 128 *  64;
    const int n3 = NG * 9 *  64 *  32;
    const int n4 = NG * 9 *  32 *  24;
    w_reorder<512, 128, 128><<<(n1 + 255) / 256, 256>>>(W1, p_wr1);
    w_reorder<128,  64,  64><<<(n2 + 255) / 256, 256>>>(W2, p_wr2);
    w_reorder< 64,  32,  32><<<(n3 + 255) / 256, 256>>>(W3, p_wr3);
    w_reorder< 32,  18,  24><<<(n4 + 255) / 256, 256>>>(W4, p_wr4);

    hwc_concat_kernel<<<dim3(NPIX / 32, 512 / 32), dim3(32, 8)>>>(gar, cond);

    k1<<<dim3(32, 2, NG), 256, smem_bytes(64)>>>(p_hwcin, p_wr1, b1, p_hwc1);
    k2<<<dim3(32, 1, NG), 256, smem_bytes(64)>>>(p_hwc1,  p_wr2, b2, p_hwc2);
    k3<<<dim3(32, 1, NG), 256, smem_bytes(32)>>>(p_hwc2,  p_wr3, b3, p_hwc3);
    k4<<<dim3(32, 1, NG), 256, smem_bytes(24)>>>(p_hwc3,  p_wr4, b4, p_oa);

    passA_kernel<<<(NK * NPIX + 255) / 256, 256>>>();
    passC_kernel<<<dim3(HW, 16), dim3(64, 4)>>>(mask, out);
}

// round 8
// speedup vs baseline: 3.7553x; 1.2688x over previous
#include <cuda_runtime.h>
#include <cstdint>
#include <cstddef>

#define HW    64
#define NPIX  4096
#define NG    8
#define NK    6

// ---------------- scratch (device globals; no allocation anywhere) -------------
__device__ __align__(1024) float g_hwcin[NPIX * 512];          // concat input, HWC
__device__ __align__(1024) float g_hwc1 [NG * NPIX * 128];
__device__ __align__(1024) float g_hwc2 [NG * NPIX *  64];
__device__ __align__(1024) float g_hwc3 [NG * NPIX *  32];
__device__ __align__(1024) float g_oa   [NG * 18 * NPIX];      // conv4 out NCHW
__device__ __align__(16)   float g_sx [NG * NK * NPIX];
__device__ __align__(16)   float g_sy [NG * NK * NPIX];
__device__ __align__(16)   float g_at [NG * NK * NPIX];
__device__ __align__(1024) float g_wr1[NG * 9 * 512 * 128];    // tf32 weights [g][tap][ci][cop]
__device__ __align__(1024) float g_wr2[NG * 9 * 128 *  64];
__device__ __align__(1024) float g_wr3[NG * 9 *  64 *  32];
__device__ __align__(1024) float g_wr4[NG * 9 *  32 *  24];

__device__ __forceinline__ uint32_t cvt_tf32(float f) {
    uint32_t u;
    asm("cvt.rna.tf32.f32 %0, %1;" : "=r"(u) : "f"(f));
    return u;
}
__device__ __forceinline__ uint32_t smem_u32(const void* p) {
    uint32_t a;
    asm("{ .reg .u64 t; cvta.to.shared.u64 t, %1; cvt.u32.u64 %0, t; }"
        : "=r"(a) : "l"(p));
    return a;
}
__device__ __forceinline__ void cp16(uint32_t dst, const void* src) {
    asm volatile("cp.async.ca.shared.global [%0], [%1], 16;"
                 :: "r"(dst), "l"(src) : "memory");
}

// ---------------- weight reorder: W[g][co][ci][3][3] -> Wr[g][tap][ci][COP] ------
template <int CI, int COUT, int COP>
__global__ void w_reorder(const float* __restrict__ w, float* __restrict__ wr) {
    const int total = NG * 9 * CI * COP;
    int i = blockIdx.x * blockDim.x + threadIdx.x;
    if (i >= total) return;
    int co  = i % COP;       int t = i / COP;
    int ci  = t % CI;        t /= CI;
    int tap = t % 9;         int g = t / 9;
    float v = 0.f;
    if (co < COUT) v = w[(((size_t)g * COUT + co) * CI + ci) * 9 + tap];
    reinterpret_cast<uint32_t*>(wr)[i] = cvt_tf32(v);
}

// ---------------- concat+transpose: [C][HW] x2 -> hwcin[p][512] ------------------
__global__ void hwc_concat_kernel(const float* __restrict__ gar,
                                  const float* __restrict__ cond) {
    __shared__ float t[32][33];
    int p  = blockIdx.x * 32 + threadIdx.x;
    int c0 = blockIdx.y * 32;
    const float* src = (c0 < 256) ? gar + (size_t)c0 * NPIX
                                  : cond + (size_t)(c0 - 256) * NPIX;
    #pragma unroll
    for (int j = 0; j < 32; j += 8)
        t[threadIdx.y + j][threadIdx.x] = src[(size_t)(threadIdx.y + j) * NPIX + p];
    __syncthreads();
    int p2 = blockIdx.x * 32 + threadIdx.y;
    int c  = c0 + threadIdx.x;
    #pragma unroll
    for (int j = 0; j < 32; j += 8)
        g_hwcin[(size_t)(p2 + j) * 512 + c] = t[threadIdx.x][threadIdx.y + j];
}

// ---------------- tf32 mma.sync implicit-GEMM 3x3 conv ---------------------------
template <int CI, int COUT, int COP, int COTILE, int WPX,
          bool RELU, bool OUT_HWC, bool GRP_IN>
__global__ __launch_bounds__(256, 2)
void gemm_conv(const float* __restrict__ hwc, const float* __restrict__ wr,
               const float* __restrict__ bias, float* __restrict__ outp) {
    constexpr int WCO    = 8 / WPX;
    constexpr int WarpPx = 128 / WPX;
    constexpr int MT     = WarpPx / 16;
    constexpr int WarpCo = COTILE / WCO;
    constexpr int NT     = WarpCo / 8;
    constexpr int BS     = (COTILE <= 32) ? 40 : 72;   // B smem row stride (floats)
    constexpr int NCC    = CI / 32;
    constexpr int NTOT   = NCC * 9;
    constexpr int AW     = 264 * 36;                   // halo tile words
    constexpr int BW     = 32 * BS;
    constexpr int NB4    = 32 * COTILE / 4;            // float4s per B stage
    constexpr int NBT    = (NB4 + 255) / 256;

    extern __shared__ float sm[];
    float* sA = sm;              // [2][AW]
    float* sB = sm + 2 * AW;     // [2][BW]

    const int tid = threadIdx.x, lane = tid & 31, wid = tid >> 5;
    const int g   = blockIdx.z;
    const int cob = blockIdx.y * COTILE;
    const int r0  = blockIdx.x * 2;
    const int p0  = blockIdx.x * 128;

    const float* inb = GRP_IN ? hwc + (size_t)g * NPIX * CI : hwc;
    const float* wb  = wr + (size_t)g * 9 * CI * COP;

    const int wco = wid % WCO, wpx = wid / WCO;
    const int r4  = lane >> 2, l4 = lane & 3;
    const uint32_t sBu = smem_u32(sB);

    // ---- prologue: stage halo chunk 0 + B iter 0 ----
    for (int it = tid; it < 264 * 8; it += 256) {
        int pos = it >> 3, cf = it & 7;
        int hr = pos / 66, hc = pos - hr * 66;
        int y = r0 - 1 + hr, x = hc - 1;
        float4 v = make_float4(0.f, 0.f, 0.f, 0.f);
        if ((unsigned)y < 64u && (unsigned)x < 64u)
            v = *(const float4*)(inb + (size_t)(y * HW + x) * CI + cf * 4);
        uint32_t* d = (uint32_t*)(sA + pos * 36 + cf * 4);
        d[0] = cvt_tf32(v.x); d[1] = cvt_tf32(v.y);
        d[2] = cvt_tf32(v.z); d[3] = cvt_tf32(v.w);
    }
    #pragma unroll
    for (int t = 0; t < NBT; t++) {
        int it = tid + t * 256;
        if (it < NB4) {
            int ci = it / (COTILE / 4), cf = it - ci * (COTILE / 4);
            float4 v = *(const float4*)(wb + (size_t)ci * COP + cob + cf * 4);
            *(float4*)(sB + ci * BS + cf * 4) = v;
        }
    }
    __syncthreads();

    float acc[MT][NT][4];
    #pragma unroll
    for (int mt = 0; mt < MT; mt++)
        #pragma unroll
        for (int nt = 0; nt < NT; nt++)
            #pragma unroll
            for (int q = 0; q < 4; q++) acc[mt][nt][q] = 0.f;

    for (int c = 0; c < NTOT; c++) {
        const int cc = c / 9, tap = c - cc * 9;
        const int c1 = c + 1;

        // -- async-prefetch B(c+1) straight into the other buffer --
        if (c1 < NTOT) {
            int cc2 = c1 / 9, tap2 = c1 - cc2 * 9;
            const float* bsrc = wb + ((size_t)tap2 * CI + cc2 * 32) * COP + cob;
            uint32_t dstb = sBu + (uint32_t)((c1 & 1) * BW) * 4u;
            #pragma unroll
            for (int t = 0; t < NBT; t++) {
                int it = tid + t * 256;
                if (it < NB4) {
                    int ci = it / (COTILE / 4), cf = it - ci * (COTILE / 4);
                    cp16(dstb + (uint32_t)(ci * BS + cf * 4) * 4u,
                         bsrc + (size_t)ci * COP + cf * 4);
                }
            }
        }
        asm volatile("cp.async.commit_group;" ::: "memory");

        // -- prefetch A slice 'tap' of chunk cc+1 (30 pos x 8 cf = 240 items) --
        float4 arg = make_float4(0.f, 0.f, 0.f, 0.f);
        int apos = -1, acf = 0;
        if (cc + 1 < NCC && tid < 240) {
            int pos = tap * 30 + (tid >> 3);
            if (pos < 264) {
                apos = pos; acf = tid & 7;
                int hr = pos / 66, hc = pos - hr * 66;
                int y = r0 - 1 + hr, x = hc - 1;
                if ((unsigned)y < 64u && (unsigned)x < 64u)
                    arg = *(const float4*)(inb + (size_t)(y * HW + x) * CI
                                           + (cc + 1) * 32 + acf * 4);
            }
        }

        // -- compute current (cc, tap) --
        const uint32_t* uA = (const uint32_t*)(sA + (cc & 1) * AW);
        const uint32_t* uB = (const uint32_t*)(sB + (c  & 1) * BW);
        const int dy = tap / 3, dx = tap - dy * 3;
        const int dtap = (dy * 66 + dx) * 36;
        int abase[MT], bbase[NT];
        #pragma unroll
        for (int mt = 0; mt < MT; mt++) {
            int pb = wpx * WarpPx + mt * 16;
            abase[mt] = dtap + ((pb >> 6) * 66 + (pb & 63) + r4) * 36 + l4;
        }
        #pragma unroll
        for (int nt = 0; nt < NT; nt++)
            bbase[nt] = l4 * BS + wco * WarpCo + nt * 8 + r4;

        #pragma unroll
        for (int ks = 0; ks < 4; ks++) {
            uint32_t af[MT][4], bf[NT][2];
            #pragma unroll
            for (int mt = 0; mt < MT; mt++) {
                int a0 = abase[mt] + ks * 8;
                af[mt][0] = uA[a0];
                af[mt][1] = uA[a0 + 8 * 36];
                af[mt][2] = uA[a0 + 4];
                af[mt][3] = uA[a0 + 8 * 36 + 4];
            }
            #pragma unroll
            for (int nt = 0; nt < NT; nt++) {
                int b0 = bbase[nt] + ks * 8 * BS;
                bf[nt][0] = uB[b0];
                bf[nt][1] = uB[b0 + 4 * BS];
            }
            #pragma unroll
            for (int mt = 0; mt < MT; mt++)
                #pragma unroll
                for (int nt = 0; nt < NT; nt++)
                    asm volatile(
                        "mma.sync.aligned.m16n8k8.row.col.f32.tf32.tf32.f32 "
                        "{%0,%1,%2,%3}, {%4,%5,%6,%7}, {%8,%9}, {%0,%1,%2,%3};"
                        : "+f"(acc[mt][nt][0]), "+f"(acc[mt][nt][1]),
                          "+f"(acc[mt][nt][2]), "+f"(acc[mt][nt][3])
                        : "r"(af[mt][0]), "r"(af[mt][1]), "r"(af[mt][2]), "r"(af[mt][3]),
                          "r"(bf[nt][0]), "r"(bf[nt][1]));
        }

        // -- commit prefetched A slice --
        if (apos >= 0) {
            uint32_t* d = (uint32_t*)(sA + ((cc + 1) & 1) * AW + apos * 36 + acf * 4);
            d[0] = cvt_tf32(arg.x); d[1] = cvt_tf32(arg.y);
            d[2] = cvt_tf32(arg.z); d[3] = cvt_tf32(arg.w);
        }
        asm volatile("cp.async.wait_group 0;" ::: "memory");
        __syncthreads();
    }

    // ---- epilogue: bias + leaky-ReLU + store ----
    #pragma unroll
    for (int mt = 0; mt < MT; mt++) {
        int pxl = wpx * WarpPx + mt * 16 + r4;
        #pragma unroll
        for (int nt = 0; nt < NT; nt++) {
            int co = cob + wco * WarpCo + nt * 8 + 2 * l4;
            float v0 = acc[mt][nt][0], v1 = acc[mt][nt][1];
            float v2 = acc[mt][nt][2], v3 = acc[mt][nt][3];
            if (OUT_HWC) {
                float b0 = bias[g * COUT + co], b1 = bias[g * COUT + co + 1];
                v0 += b0; v1 += b1; v2 += b0; v3 += b1;
                if (RELU) {
                    v0 = (v0 >= 0.f) ? v0 : 0.1f * v0;
                    v1 = (v1 >= 0.f) ? v1 : 0.1f * v1;
                    v2 = (v2 >= 0.f) ? v2 : 0.1f * v2;
                    v3 = (v3 >= 0.f) ? v3 : 0.1f * v3;
                }
                float* ob = outp + (size_t)g * NPIX * COUT;
                *(float2*)(ob + (size_t)(p0 + pxl) * COUT + co)     = make_float2(v0, v1);
                *(float2*)(ob + (size_t)(p0 + pxl + 8) * COUT + co) = make_float2(v2, v3);
            } else {
                #pragma unroll
                for (int s = 0; s < 2; s++) {
                    int c2 = co + s;
                    if (c2 < COUT) {
                        float bv = bias[g * COUT + c2];
                        float va = (s ? v1 : v0) + bv;
                        float vb = (s ? v3 : v2) + bv;
                        if (RELU) {
                            va = (va >= 0.f) ? va : 0.1f * va;
                            vb = (vb >= 0.f) ? vb : 0.1f * vb;
                        }
                        float* ob = outp + ((size_t)g * COUT + c2) * NPIX + p0;
                        ob[pxl]     = va;
                        ob[pxl + 8] = vb;
                    }
                }
            }
        }
    }
}

// ---------------- pass A: softmax attention + sample coords --------------------
__global__ void passA_kernel() {
    int idx = blockIdx.x * blockDim.x + threadIdx.x;
    if (idx >= NK * NPIX) return;
    int p = idx & (NPIX - 1);
    int k = idx >> 12;
    int jx = p & 63, jy = p >> 6;

    float a[NG]; float mx = -1e30f;
    #pragma unroll
    for (int g = 0; g < NG; g++) {
        a[g] = g_oa[(size_t)(g * 18 + 12 + k) * NPIX + p];
        mx = fmaxf(mx, a[g]);
    }
    float s = 0.f;
    #pragma unroll
    for (int g = 0; g < NG; g++) { a[g] = __expf(a[g] - mx); s += a[g]; }
    float inv = 1.f / s;
    const float sc = 64.f / 63.f;
    #pragma unroll
    for (int g = 0; g < NG; g++) {
        int sidx = (g * NK + k) * NPIX + p;
        g_at[sidx] = a[g] * inv;
        float ox = g_oa[(size_t)(g * 18 + 2 * k    ) * NPIX + p];
        float oy = g_oa[(size_t)(g * 18 + 2 * k + 1) * NPIX + p];
        g_sx[sidx] = fminf(fmaxf((jx + ox) * sc - 0.5f, 0.f), 63.f);
        g_sy[sidx] = fminf(fmaxf((jy + oy) * sc - 0.5f, 0.f), 63.f);
    }
}

// ---------------- pass C: warp-per-pixel gather, channel-major lanes -------------
// Warp w of block b owns pixel p = b*8+w. Lane l owns channels {4l..4l+3} and
// {128+4l..128+4l+3}: every corner load is a fully coalesced 512B transaction,
// and the 48 samples of a pixel reuse a tiny L1-resident neighborhood.
__global__ __launch_bounds__(256)
void passC_kernel(const float* __restrict__ mask, float* __restrict__ out) {
    const int lane = threadIdx.x & 31, wid = threadIdx.x >> 5;
    const int p  = blockIdx.x * 8 + wid;
    const int c0 = lane * 4;

    float4 acc0 = make_float4(0.f, 0.f, 0.f, 0.f);
    float4 acc1 = make_float4(0.f, 0.f, 0.f, 0.f);

    #pragma unroll 1
    for (int g = 0; g < NG; g++) {
        float4 pa0 = make_float4(0.f, 0.f, 0.f, 0.f);
        float4 pa1 = make_float4(0.f, 0.f, 0.f, 0.f);
        #pragma unroll 2
        for (int k = 0; k < NK; k++) {
            int s = (g * NK + k) * NPIX + p;
            float sx = g_sx[s], sy = g_sy[s], a = g_at[s];
            float x0f = floorf(sx), y0f = floorf(sy);
            int x0 = (int)x0f, y0 = (int)y0f;
            float wx = sx - x0f, wy = sy - y0f;
            int x1 = min(x0 + 1, 63), y1 = min(y0 + 1, 63);
            float w00 = a * (1.f - wy) * (1.f - wx);
            float w01 = a * (1.f - wy) * wx;
            float w10 = a * wy * (1.f - wx);
            float w11 = a * wy * wx;
            const float* r00 = g_hwcin + (size_t)(y0 * HW + x0) * 512 + c0;
            const float* r01 = g_hwcin + (size_t)(y0 * HW + x1) * 512 + c0;
            const float* r10 = g_hwcin + (size_t)(y1 * HW + x0) * 512 + c0;
            const float* r11 = g_hwcin + (size_t)(y1 * HW + x1) * 512 + c0;
            float4 a00 = *(const float4*)(r00);
            float4 a01 = *(const float4*)(r01);
            float4 a10 = *(const float4*)(r10);
            float4 a11 = *(const float4*)(r11);
            pa0.x += w00 * a00.x + w01 * a01.x + w10 * a10.x + w11 * a11.x;
            pa0.y += w00 * a00.y + w01 * a01.y + w10 * a10.y + w11 * a11.y;
            pa0.z += w00 * a00.z + w01 * a01.z + w10 * a10.z + w11 * a11.z;
            pa0.w += w00 * a00.w + w01 * a01.w + w10 * a10.w + w11 * a11.w;
            float4 b00 = *(const float4*)(r00 + 128);
            float4 b01 = *(const float4*)(r01 + 128);
            float4 b10 = *(const float4*)(r10 + 128);
            float4 b11 = *(const float4*)(r11 + 128);
            pa1.x += w00 * b00.x + w01 * b01.x + w10 * b10.x + w11 * b11.x;
            pa1.y += w00 * b00.y + w01 * b01.y + w10 * b10.y + w11 * b11.y;
            pa1.z += w00 * b00.z + w01 * b01.z + w10 * b10.z + w11 * b11.z;
            pa1.w += w00 * b00.w + w01 * b01.w + w10 * b10.w + w11 * b11.w;
        }
        const float4 m0 = *(const float4*)(mask + g * 256 + c0);
        const float4 m1 = *(const float4*)(mask + g * 256 + 128 + c0);
        acc0.x += m0.x * pa0.x; acc0.y += m0.y * pa0.y;
        acc0.z += m0.z * pa0.z; acc0.w += m0.w * pa0.w;
        acc1.x += m1.x * pa1.x; acc1.y += m1.y * pa1.y;
        acc1.z += m1.z * pa1.z; acc1.w += m1.w * pa1.w;
    }
    out[(size_t)(c0 + 0) * NPIX + p] = acc0.x;
    out[(size_t)(c0 + 1) * NPIX + p] = acc0.y;
    out[(size_t)(c0 + 2) * NPIX + p] = acc0.z;
    out[(size_t)(c0 + 3) * NPIX + p] = acc0.w;
    out[(size_t)(128 + c0 + 0) * NPIX + p] = acc1.x;
    out[(size_t)(128 + c0 + 1) * NPIX + p] = acc1.y;
    out[(size_t)(128 + c0 + 2) * NPIX + p] = acc1.z;
    out[(size_t)(128 + c0 + 3) * NPIX + p] = acc1.w;
}

// ---------------- host launcher -------------------------------------------------
static float* sym_addr(const void* symbol) {
    void* p = nullptr;
    cudaGetSymbolAddress(&p, symbol);
    return reinterpret_cast<float*>(p);
}

static constexpr int smem_bytes(int cotile) {
    int bs = (cotile <= 32) ? 40 : 72;
    return (2 * 264 * 36 + 2 * 32 * bs) * 4;
}

extern "C" void kernel_launch(void* const* d_in, const int* in_sizes, int n_in,
                              void* d_out, int out_size) {
    const float* gar  = (const float*)d_in[0];
    const float* cond = (const float*)d_in[1];
    const float* mask = (const float*)d_in[2];
    const float* W1 = (const float*)d_in[3];
    const float* b1 = (const float*)d_in[4];
    const float* W2 = (const float*)d_in[5];
    const float* b2 = (const float*)d_in[6];
    const float* W3 = (const float*)d_in[7];
    const float* b3 = (const float*)d_in[8];
    const float* W4 = (const float*)d_in[9];
    const float* b4 = (const float*)d_in[10];
    float* out = (float*)d_out;

    float* p_hwcin = sym_addr(g_hwcin);
    float* p_hwc1  = sym_addr(g_hwc1);
    float* p_hwc2  = sym_addr(g_hwc2);
    float* p_hwc3  = sym_addr(g_hwc3);
    float* p_oa    = sym_addr(g_oa);
    float* p_wr1   = sym_addr(g_wr1);
    float* p_wr2   = sym_addr(g_wr2);
    float* p_wr3   = sym_addr(g_wr3);
    float* p_wr4   = sym_addr(g_wr4);

    auto k1 = gemm_conv<512, 128, 128, 64, 4, true,  true,  false>;
    auto k2 = gemm_conv<128,  64,  64, 64, 4, true,  true,  true >;
    auto k3 = gemm_conv< 64,  32,  32, 32, 4, true,  true,  true >;
    auto k4 = gemm_conv< 32,  18,  24, 24, 8, false, false, true >;
    cudaFuncSetAttribute(k1, cudaFuncAttributeMaxDynamicSharedMemorySize, smem_bytes(64));
    cudaFuncSetAttribute(k2, cudaFuncAttributeMaxDynamicSharedMemorySize, smem_bytes(64));
    cudaFuncSetAttribute(k3, cudaFuncAttributeMaxDynamicSharedMemorySize, smem_bytes(32));
    cudaFuncSetAttribute(k4, cudaFuncAttributeMaxDynamicSharedMemorySize, smem_bytes(24));

    const int n1 = NG * 9 * 512 * 128;
    const int n2 = NG * 9 * 128 *  64;
    const int n3 = NG * 9 *  64 *  32;
    const int n4 = NG * 9 *  32 *  24;
    w_reorder<512, 128, 128><<<(n1 + 255) / 256, 256>>>(W1, p_wr1);
    w_reorder<128,  64,  64><<<(n2 + 255) / 256, 256>>>(W2, p_wr2);
    w_reorder< 64,  32,  32><<<(n3 + 255) / 256, 256>>>(W3, p_wr3);
    w_reorder< 32,  18,  24><<<(n4 + 255) / 256, 256>>>(W4, p_wr4);

    hwc_concat_kernel<<<dim3(NPIX / 32, 512 / 32), dim3(32, 8)>>>(gar, cond);

    k1<<<dim3(32, 2, NG), 256, smem_bytes(64)>>>(p_hwcin, p_wr1, b1, p_hwc1);
    k2<<<dim3(32, 1, NG), 256, smem_bytes(64)>>>(p_hwc1,  p_wr2, b2, p_hwc2);
    k3<<<dim3(32, 1, NG), 256, smem_bytes(32)>>>(p_hwc2,  p_wr3, b3, p_hwc3);
    k4<<<dim3(32, 1, NG), 256, smem_bytes(24)>>>(p_hwc3,  p_wr4, b4, p_oa);

    passA_kernel<<<(NK * NPIX + 255) / 256, 256>>>();
    passC_kernel<<<512, 256>>>(mask, out);
}

// round 9
// speedup vs baseline: 5.5654x; 1.4820x over previous
#include <cuda_runtime.h>
#include <cuda_bf16.h>
#include <cstdint>
#include <cstddef>

#define HW    64
#define NPIX  4096
#define NG    8
#define NK    6

// ---------------- scratch (device globals; no allocation anywhere) -------------
__device__ __align__(1024) float g_hwcin[NPIX * 512];            // concat input, HWC fp32
__device__ __align__(1024) __nv_bfloat16 g_b1[NG * NPIX * 128];  // activations bf16 HWC
__device__ __align__(1024) __nv_bfloat16 g_b2[NG * NPIX *  64];
__device__ __align__(1024) __nv_bfloat16 g_b3[NG * NPIX *  32];
__device__ __align__(1024) float g_oa [NG * 18 * NPIX];          // conv4 out NCHW fp32
__device__ __align__(16)   float g_sx [NG * NK * NPIX];
__device__ __align__(16)   float g_sy [NG * NK * NPIX];
__device__ __align__(16)   float g_at [NG * NK * NPIX];
__device__ __align__(1024) __nv_bfloat16 g_wb1[NG * 9 * 128 * 512];  // [g][tap][co][ci]
__device__ __align__(1024) __nv_bfloat16 g_wb2[NG * 9 *  64 * 128];
__device__ __align__(1024) __nv_bfloat16 g_wb3[NG * 9 *  32 *  64];
__device__ __align__(1024) __nv_bfloat16 g_wb4[NG * 9 *  24 *  32];

__device__ __forceinline__ uint32_t smem_u32(const void* p) {
    uint32_t a;
    asm("{ .reg .u64 t; cvta.to.shared.u64 t, %1; cvt.u32.u64 %0, t; }"
        : "=r"(a) : "l"(p));
    return a;
}
__device__ __forceinline__ void cp16(uint32_t dst, const void* src) {
    asm volatile("cp.async.ca.shared.global [%0], [%1], 16;"
                 :: "r"(dst), "l"(src) : "memory");
}
__device__ __forceinline__ uint32_t bf2pack(float lo, float hi) {
    __nv_bfloat162 b = __floats2bfloat162_rn(lo, hi);
    return *reinterpret_cast<uint32_t*>(&b);
}

// ------ tiled weight reorder: W[g][co][ci][3][3] -> Wb[g][tap][co(COP)][ci] bf16 ----
// Block 256 = 8 co x 32 ci; reads 9-contiguous floats per thread (lanes over ci,
// fully coalesced); writes packed bf16 pairs, lanes over ci (coalesced).
template <int CI, int COUT, int COP>
__global__ void w_reorder_t(const float* __restrict__ w, __nv_bfloat16* __restrict__ wr) {
    __shared__ __nv_bfloat16 s[9][8][34];
    const int tid = threadIdx.x;
    const int cib = blockIdx.x * 32, cob = blockIdx.y * 8, g = blockIdx.z;
    const int coq = tid >> 5, ci = tid & 31;
    const int co  = cob + coq;
    if (co < COUT) {
        const float* src = w + (((size_t)g * COUT + co) * CI + cib + ci) * 9;
        #pragma unroll
        for (int t = 0; t < 9; t++) s[t][coq][ci] = __float2bfloat16(src[t]);
    } else {
        #pragma unroll
        for (int t = 0; t < 9; t++) s[t][coq][ci] = __float2bfloat16(0.f);
    }
    __syncthreads();
    for (int it = tid; it < 9 * 8 * 16; it += 256) {
        int row = it >> 4, wq = it & 15;
        int tap = row >> 3, col = row & 7;
        uint32_t v = (uint32_t)__bfloat16_as_ushort(s[tap][col][2 * wq]) |
                     ((uint32_t)__bfloat16_as_ushort(s[tap][col][2 * wq + 1]) << 16);
        uint32_t* dst = (uint32_t*)(wr + (((size_t)(g * 9 + tap) * COP) + cob + col) * CI + cib);
        dst[wq] = v;
    }
}

// ---------------- concat+transpose: [C][HW] x2 -> hwcin[p][512] fp32 -------------
__global__ void hwc_concat_kernel(const float* __restrict__ gar,
                                  const float* __restrict__ cond) {
    __shared__ float t[32][33];
    int p  = blockIdx.x * 32 + threadIdx.x;
    int c0 = blockIdx.y * 32;
    const float* src = (c0 < 256) ? gar + (size_t)c0 * NPIX
                                  : cond + (size_t)(c0 - 256) * NPIX;
    #pragma unroll
    for (int j = 0; j < 32; j += 8)
        t[threadIdx.y + j][threadIdx.x] = src[(size_t)(threadIdx.y + j) * NPIX + p];
    __syncthreads();
    int p2 = blockIdx.x * 32 + threadIdx.y;
    int c  = c0 + threadIdx.x;
    #pragma unroll
    for (int j = 0; j < 32; j += 8)
        g_hwcin[(size_t)(p2 + j) * 512 + c] = t[threadIdx.x][threadIdx.y + j];
}

// ---------------- bf16 mma.sync implicit-GEMM 3x3 conv ---------------------------
// CTA: 128 px (2 image rows) x COTILE co. Halo (6x66 pos x 32 ci bf16) staged once
// per ci-chunk, reused by 9 taps. A stride = 20 words (conflict-free fragments).
template <int CI, int COUT, int COP, int COTILE, int WPX,
          bool RELU, bool OUT_HWC, bool GRP_IN, bool IN_BF16>
__global__ __launch_bounds__(256, 2)
void gemm_conv(const void* __restrict__ inp, const __nv_bfloat16* __restrict__ wr,
               const float* __restrict__ bias, void* __restrict__ outp) {
    constexpr int WCO    = 8 / WPX;
    constexpr int WarpPx = 128 / WPX;
    constexpr int MT     = WarpPx / 16;
    constexpr int WarpCo = COTILE / WCO;
    constexpr int NT     = WarpCo / 8;
    constexpr int NCC    = CI / 32;
    constexpr int NTOT   = NCC * 9;
    constexpr int AW     = 264 * 20;           // words per A buffer
    constexpr int BW     = COTILE * 20;        // words per B buffer

    extern __shared__ uint32_t smu[];
    uint32_t* sA = smu;            // [2][AW]
    uint32_t* sB = smu + 2 * AW;   // [2][BW]

    const int tid = threadIdx.x, lane = tid & 31, wid = tid >> 5;
    const int g   = blockIdx.z;
    const int cob = blockIdx.y * COTILE;
    const int r0  = blockIdx.x * 2;
    const int p0  = blockIdx.x * 128;

    const float*         inf = (const float*)inp         + (GRP_IN ? (size_t)g * NPIX * CI : 0);
    const __nv_bfloat16* ing = (const __nv_bfloat16*)inp + (GRP_IN ? (size_t)g * NPIX * CI : 0);
    const __nv_bfloat16* wb  = wr + (size_t)g * 9 * COP * CI;

    const int wco = wid % WCO, wpx = wid / WCO;
    const int r4  = lane >> 2, l4 = lane & 3;
    const uint32_t sBu = smem_u32(sB);

    // ---- prologue: stage halo chunk 0 + B iter 0 ----
    if constexpr (IN_BF16) {
        for (int it = tid; it < 264 * 4; it += 256) {
            int pos = it >> 2, cf = it & 3;
            int hr = pos / 66, hc = pos - hr * 66;
            int y = r0 - 1 + hr, x = hc - 1;
            uint4 v = make_uint4(0, 0, 0, 0);
            if ((unsigned)y < 64u && (unsigned)x < 64u)
                v = *(const uint4*)(ing + (size_t)(y * HW + x) * CI + cf * 8);
            *(uint4*)(sA + pos * 20 + cf * 4) = v;
        }
    } else {
        for (int it = tid; it < 264 * 8; it += 256) {
            int pos = it >> 3, cf = it & 7;
            int hr = pos / 66, hc = pos - hr * 66;
            int y = r0 - 1 + hr, x = hc - 1;
            float4 v = make_float4(0.f, 0.f, 0.f, 0.f);
            if ((unsigned)y < 64u && (unsigned)x < 64u)
                v = *(const float4*)(inf + (size_t)(y * HW + x) * CI + cf * 4);
            uint32_t* d = sA + pos * 20 + cf * 2;
            d[0] = bf2pack(v.x, v.y);
            d[1] = bf2pack(v.z, v.w);
        }
    }
    for (int it = tid; it < COTILE * 4; it += 256) {
        int co = it >> 2, cf = it & 3;
        uint4 v = *(const uint4*)(wb + (size_t)(cob + co) * CI + cf * 8);
        *(uint4*)(sB + co * 20 + cf * 4) = v;
    }
    __syncthreads();

    float acc[MT][NT][4];
    #pragma unroll
    for (int mt = 0; mt < MT; mt++)
        #pragma unroll
        for (int nt = 0; nt < NT; nt++)
            #pragma unroll
            for (int q = 0; q < 4; q++) acc[mt][nt][q] = 0.f;

    for (int c = 0; c < NTOT; c++) {
        const int cc = c / 9, tap = c - cc * 9;
        const int c1 = c + 1;

        // -- async-prefetch B(c+1) into the other buffer --
        if (c1 < NTOT) {
            int cc2 = c1 / 9, tap2 = c1 - cc2 * 9;
            const __nv_bfloat16* bsrc = wb + (size_t)tap2 * COP * CI + cc2 * 32;
            uint32_t dstb = sBu + (uint32_t)((c1 & 1) * BW) * 4u;
            for (int it = tid; it < COTILE * 4; it += 256) {
                int co = it >> 2, cf = it & 3;
                cp16(dstb + (uint32_t)(co * 20 + cf * 4) * 4u,
                     bsrc + (size_t)(cob + co) * CI + cf * 8);
            }
        }
        asm volatile("cp.async.commit_group;" ::: "memory");

        // -- prefetch A slice 'tap' of chunk cc+1 --
        float4 argf = make_float4(0.f, 0.f, 0.f, 0.f);
        uint4  argb = make_uint4(0, 0, 0, 0);
        int apos = -1, acf = 0;
        if (cc + 1 < NCC) {
            if constexpr (IN_BF16) {
                if (tid < 120) {
                    int pos = tap * 30 + (tid >> 2);
                    if (pos < 264) {
                        apos = pos; acf = tid & 3;
                        int hr = pos / 66, hc = pos - hr * 66;
                        int y = r0 - 1 + hr, x = hc - 1;
                        if ((unsigned)y < 64u && (unsigned)x < 64u)
                            argb = *(const uint4*)(ing + (size_t)(y * HW + x) * CI
                                                   + (cc + 1) * 32 + acf * 8);
                    }
                }
            } else {
                if (tid < 240) {
                    int pos = tap * 30 + (tid >> 3);
                    if (pos < 264) {
                        apos = pos; acf = tid & 7;
                        int hr = pos / 66, hc = pos - hr * 66;
                        int y = r0 - 1 + hr, x = hc - 1;
                        if ((unsigned)y < 64u && (unsigned)x < 64u)
                            argf = *(const float4*)(inf + (size_t)(y * HW + x) * CI
                                                    + (cc + 1) * 32 + acf * 4);
                    }
                }
            }
        }

        // -- compute current (cc, tap) --
        const uint32_t* uA = sA + (cc & 1) * AW;
        const uint32_t* uB = sB + (c  & 1) * BW;
        const int dy = tap / 3, dx = tap - dy * 3;
        const int dtap = (dy * 66 + dx) * 20;
        int abase[MT], bbase[NT];
        #pragma unroll
        for (int mt = 0; mt < MT; mt++) {
            int pb = wpx * WarpPx + mt * 16;
            abase[mt] = dtap + ((pb >> 6) * 66 + (pb & 63) + r4) * 20 + l4;
        }
        #pragma unroll
        for (int nt = 0; nt < NT; nt++)
            bbase[nt] = (wco * WarpCo + nt * 8 + r4) * 20 + l4;

        #pragma unroll
        for (int ks = 0; ks < 2; ks++) {
            const int k8 = ks * 8;
            uint32_t af[MT][4], bf[NT][2];
            #pragma unroll
            for (int mt = 0; mt < MT; mt++) {
                int a0 = abase[mt] + k8;
                af[mt][0] = uA[a0];
                af[mt][1] = uA[a0 + 160];
                af[mt][2] = uA[a0 + 4];
                af[mt][3] = uA[a0 + 164];
            }
            #pragma unroll
            for (int nt = 0; nt < NT; nt++) {
                int b0 = bbase[nt] + k8;
                bf[nt][0] = uB[b0];
                bf[nt][1] = uB[b0 + 4];
            }
            #pragma unroll
            for (int mt = 0; mt < MT; mt++)
                #pragma unroll
                for (int nt = 0; nt < NT; nt++)
                    asm volatile(
                        "mma.sync.aligned.m16n8k16.row.col.f32.bf16.bf16.f32 "
                        "{%0,%1,%2,%3}, {%4,%5,%6,%7}, {%8,%9}, {%0,%1,%2,%3};"
                        : "+f"(acc[mt][nt][0]), "+f"(acc[mt][nt][1]),
                          "+f"(acc[mt][nt][2]), "+f"(acc[mt][nt][3])
                        : "r"(af[mt][0]), "r"(af[mt][1]), "r"(af[mt][2]), "r"(af[mt][3]),
                          "r"(bf[nt][0]), "r"(bf[nt][1]));
        }

        // -- commit prefetched A slice --
        if (apos >= 0) {
            uint32_t* d = sA + ((cc + 1) & 1) * AW + apos * 20;
            if constexpr (IN_BF16) {
                *(uint4*)(d + acf * 4) = argb;
            } else {
                d[acf * 2]     = bf2pack(argf.x, argf.y);
                d[acf * 2 + 1] = bf2pack(argf.z, argf.w);
            }
        }
        asm volatile("cp.async.wait_group 0;" ::: "memory");
        __syncthreads();
    }

    // ---- epilogue: bias + leaky-ReLU + store ----
    #pragma unroll
    for (int mt = 0; mt < MT; mt++) {
        int pxl = wpx * WarpPx + mt * 16 + r4;
        #pragma unroll
        for (int nt = 0; nt < NT; nt++) {
            int co = cob + wco * WarpCo + nt * 8 + 2 * l4;
            float v0 = acc[mt][nt][0], v1 = acc[mt][nt][1];
            float v2 = acc[mt][nt][2], v3 = acc[mt][nt][3];
            if (OUT_HWC) {
                float b0 = bias[g * COUT + co], b1 = bias[g * COUT + co + 1];
                v0 += b0; v1 += b1; v2 += b0; v3 += b1;
                if (RELU) {
                    v0 = (v0 >= 0.f) ? v0 : 0.1f * v0;
                    v1 = (v1 >= 0.f) ? v1 : 0.1f * v1;
                    v2 = (v2 >= 0.f) ? v2 : 0.1f * v2;
                    v3 = (v3 >= 0.f) ? v3 : 0.1f * v3;
                }
                __nv_bfloat16* ob = (__nv_bfloat16*)outp + (size_t)g * NPIX * COUT;
                *(uint32_t*)(ob + (size_t)(p0 + pxl) * COUT + co)     = bf2pack(v0, v1);
                *(uint32_t*)(ob + (size_t)(p0 + pxl + 8) * COUT + co) = bf2pack(v2, v3);
            } else {
                #pragma unroll
                for (int s = 0; s < 2; s++) {
                    int c2 = co + s;
                    if (c2 < COUT) {
                        float bv = bias[g * COUT + c2];
                        float va = (s ? v1 : v0) + bv;
                        float vb = (s ? v3 : v2) + bv;
                        if (RELU) {
                            va = (va >= 0.f) ? va : 0.1f * va;
                            vb = (vb >= 0.f) ? vb : 0.1f * vb;
                        }
                        float* ob = (float*)outp + ((size_t)g * COUT + c2) * NPIX + p0;
                        ob[pxl]     = va;
                        ob[pxl + 8] = vb;
                    }
                }
            }
        }
    }
}

// ---------------- pass A: softmax attention + sample coords --------------------
__global__ void passA_kernel() {
    int idx = blockIdx.x * blockDim.x + threadIdx.x;
    if (idx >= NK * NPIX) return;
    int p = idx & (NPIX - 1);
    int k = idx >> 12;
    int jx = p & 63, jy = p >> 6;

    float a[NG]; float mx = -1e30f;
    #pragma unroll
    for (int g = 0; g < NG; g++) {
        a[g] = g_oa[(size_t)(g * 18 + 12 + k) * NPIX + p];
        mx = fmaxf(mx, a[g]);
    }
    float s = 0.f;
    #pragma unroll
    for (int g = 0; g < NG; g++) { a[g] = __expf(a[g] - mx); s += a[g]; }
    float inv = 1.f / s;
    const float sc = 64.f / 63.f;
    #pragma unroll
    for (int g = 0; g < NG; g++) {
        int sidx = (g * NK + k) * NPIX + p;
        g_at[sidx] = a[g] * inv;
        float ox = g_oa[(size_t)(g * 18 + 2 * k    ) * NPIX + p];
        float oy = g_oa[(size_t)(g * 18 + 2 * k + 1) * NPIX + p];
        g_sx[sidx] = fminf(fmaxf((jx + ox) * sc - 0.5f, 0.f), 63.f);
        g_sy[sidx] = fminf(fmaxf((jy + oy) * sc - 0.5f, 0.f), 63.f);
    }
}

// ---------------- pass C: warp-per-pixel gather, channel-major lanes -------------
__global__ __launch_bounds__(256)
void passC_kernel(const float* __restrict__ mask, float* __restrict__ out) {
    const int lane = threadIdx.x & 31, wid = threadIdx.x >> 5;
    const int p  = blockIdx.x * 8 + wid;
    const int c0 = lane * 4;

    float4 acc0 = make_float4(0.f, 0.f, 0.f, 0.f);
    float4 acc1 = make_float4(0.f, 0.f, 0.f, 0.f);

    #pragma unroll 1
    for (int g = 0; g < NG; g++) {
        float4 pa0 = make_float4(0.f, 0.f, 0.f, 0.f);
        float4 pa1 = make_float4(0.f, 0.f, 0.f, 0.f);
        #pragma unroll 2
        for (int k = 0; k < NK; k++) {
            int s = (g * NK + k) * NPIX + p;
            float sx = g_sx[s], sy = g_sy[s], a = g_at[s];
            float x0f = floorf(sx), y0f = floorf(sy);
            int x0 = (int)x0f, y0 = (int)y0f;
            float wx = sx - x0f, wy = sy - y0f;
            int x1 = min(x0 + 1, 63), y1 = min(y0 + 1, 63);
            float w00 = a * (1.f - wy) * (1.f - wx);
            float w01 = a * (1.f - wy) * wx;
            float w10 = a * wy * (1.f - wx);
            float w11 = a * wy * wx;
            const float* r00 = g_hwcin + (size_t)(y0 * HW + x0) * 512 + c0;
            const float* r01 = g_hwcin + (size_t)(y0 * HW + x1) * 512 + c0;
            const float* r10 = g_hwcin + (size_t)(y1 * HW + x0) * 512 + c0;
            const float* r11 = g_hwcin + (size_t)(y1 * HW + x1) * 512 + c0;
            float4 a00 = *(const float4*)(r00);
            float4 a01 = *(const float4*)(r01);
            float4 a10 = *(const float4*)(r10);
            float4 a11 = *(const float4*)(r11);
            pa0.x += w00 * a00.x + w01 * a01.x + w10 * a10.x + w11 * a11.x;
            pa0.y += w00 * a00.y + w01 * a01.y + w10 * a10.y + w11 * a11.y;
            pa0.z += w00 * a00.z + w01 * a01.z + w10 * a10.z + w11 * a11.z;
            pa0.w += w00 * a00.w + w01 * a01.w + w10 * a10.w + w11 * a11.w;
            float4 b00 = *(const float4*)(r00 + 128);
            float4 b01 = *(const float4*)(r01 + 128);
            float4 b10 = *(const float4*)(r10 + 128);
            float4 b11 = *(const float4*)(r11 + 128);
            pa1.x += w00 * b00.x + w01 * b01.x + w10 * b10.x + w11 * b11.x;
            pa1.y += w00 * b00.y + w01 * b01.y + w10 * b10.y + w11 * b11.y;
            pa1.z += w00 * b00.z + w01 * b01.z + w10 * b10.z + w11 * b11.z;
            pa1.w += w00 * b00.w + w01 * b01.w + w10 * b10.w + w11 * b11.w;
        }
        const float4 m0 = *(const float4*)(mask + g * 256 + c0);
        const float4 m1 = *(const float4*)(mask + g * 256 + 128 + c0);
        acc0.x += m0.x * pa0.x; acc0.y += m0.y * pa0.y;
        acc0.z += m0.z * pa0.z; acc0.w += m0.w * pa0.w;
        acc1.x += m1.x * pa1.x; acc1.y += m1.y * pa1.y;
        acc1.z += m1.z * pa1.z; acc1.w += m1.w * pa1.w;
    }
    out[(size_t)(c0 + 0) * NPIX + p] = acc0.x;
    out[(size_t)(c0 + 1) * NPIX + p] = acc0.y;
    out[(size_t)(c0 + 2) * NPIX + p] = acc0.z;
    out[(size_t)(c0 + 3) * NPIX + p] = acc0.w;
    out[(size_t)(128 + c0 + 0) * NPIX + p] = acc1.x;
    out[(size_t)(128 + c0 + 1) * NPIX + p] = acc1.y;
    out[(size_t)(128 + c0 + 2) * NPIX + p] = acc1.z;
    out[(size_t)(128 + c0 + 3) * NPIX + p] = acc1.w;
}

// ---------------- host launcher -------------------------------------------------
static void* sym_addr(const void* symbol) {
    void* p = nullptr;
    cudaGetSymbolAddress(&p, symbol);
    return p;
}

static constexpr int smem_bytes(int cotile) {
    return (2 * 264 * 20 + 2 * cotile * 20) * 4;
}

extern "C" void kernel_launch(void* const* d_in, const int* in_sizes, int n_in,
                              void* d_out, int out_size) {
    const float* gar  = (const float*)d_in[0];
    const float* cond = (const float*)d_in[1];
    const float* mask = (const float*)d_in[2];
    const float* W1 = (const float*)d_in[3];
    const float* b1 = (const float*)d_in[4];
    const float* W2 = (const float*)d_in[5];
    const float* b2 = (const float*)d_in[6];
    const float* W3 = (const float*)d_in[7];
    const float* b3 = (const float*)d_in[8];
    const float* W4 = (const float*)d_in[9];
    const float* b4 = (const float*)d_in[10];
    float* out = (float*)d_out;

    void* p_hwcin = sym_addr(g_hwcin);
    void* p_b1 = sym_addr(g_b1);
    void* p_b2 = sym_addr(g_b2);
    void* p_b3 = sym_addr(g_b3);
    void* p_oa = sym_addr(g_oa);
    __nv_bfloat16* p_wb1 = (__nv_bfloat16*)sym_addr(g_wb1);
    __nv_bfloat16* p_wb2 = (__nv_bfloat16*)sym_addr(g_wb2);
    __nv_bfloat16* p_wb3 = (__nv_bfloat16*)sym_addr(g_wb3);
    __nv_bfloat16* p_wb4 = (__nv_bfloat16*)sym_addr(g_wb4);

    auto k1 = gemm_conv<512, 128, 128, 64, 4, true,  true,  false, false>;
    auto k2 = gemm_conv<128,  64,  64, 64, 4, true,  true,  true,  true >;
    auto k3 = gemm_conv< 64,  32,  32, 32, 4, true,  true,  true,  true >;
    auto k4 = gemm_conv< 32,  18,  24, 24, 8, false, false, true,  true >;
    cudaFuncSetAttribute(k1, cudaFuncAttributeMaxDynamicSharedMemorySize, smem_bytes(64));
    cudaFuncSetAttribute(k2, cudaFuncAttributeMaxDynamicSharedMemorySize, smem_bytes(64));
    cudaFuncSetAttribute(k3, cudaFuncAttributeMaxDynamicSharedMemorySize, smem_bytes(32));
    cudaFuncSetAttribute(k4, cudaFuncAttributeMaxDynamicSharedMemorySize, smem_bytes(24));

    w_reorder_t<512, 128, 128><<<dim3(16, 16, NG), 256>>>(W1, p_wb1);
    w_reorder_t<128,  64,  64><<<dim3( 4,  8, NG), 256>>>(W2, p_wb2);
    w_reorder_t< 64,  32,  32><<<dim3( 2,  4, NG), 256>>>(W3, p_wb3);
    w_reorder_t< 32,  18,  24><<<dim3( 1,  3, NG), 256>>>(W4, p_wb4);

    hwc_concat_kernel<<<dim3(NPIX / 32, 512 / 32), dim3(32, 8)>>>(gar, cond);

    k1<<<dim3(32, 2, NG), 256, smem_bytes(64)>>>(p_hwcin, p_wb1, b1, p_b1);
    k2<<<dim3(32, 1, NG), 256, smem_bytes(64)>>>(p_b1,    p_wb2, b2, p_b2);
    k3<<<dim3(32, 1, NG), 256, smem_bytes(32)>>>(p_b2,    p_wb3, b3, p_b3);
    k4<<<dim3(32, 1, NG), 256, smem_bytes(24)>>>(p_b3,    p_wb4, b4, p_oa);

    passA_kernel<<<(NK * NPIX + 255) / 256, 256>>>();
    passC_kernel<<<512, 256>>>(mask, out);
}

// round 15
// speedup vs baseline: 7.2432x; 1.3015x over previous
#include <cuda_runtime.h>
#include <cuda_bf16.h>
#include <cstdint>
#include <cstddef>

#define HW    64
#define NPIX  4096
#define NG    8
#define NK    6

// ---------------- scratch (device globals; no allocation anywhere) -------------
__device__ __align__(1024) __nv_bfloat16 g_bin[NPIX * 512];      // concat input bf16 HWC
__device__ __align__(1024) float g_garf[NPIX * 256];             // gar fp32 HWC (passC)
__device__ __align__(1024) __nv_bfloat16 g_b1[NG * NPIX * 128];  // activations bf16 HWC
__device__ __align__(1024) __nv_bfloat16 g_b2[NG * NPIX *  64];
__device__ __align__(1024) __nv_bfloat16 g_b3[NG * NPIX *  32];
__device__ __align__(1024) float g_oa [NG * 18 * NPIX];          // conv4 out NCHW fp32
__device__ __align__(16)   float g_sx [NG * NK * NPIX];
__device__ __align__(16)   float g_sy [NG * NK * NPIX];
__device__ __align__(16)   float g_at [NG * NK * NPIX];
__device__ __align__(1024) __nv_bfloat16 g_wb1[NG * 9 * 128 * 512];  // [g][tap][co][ci]
__device__ __align__(1024) __nv_bfloat16 g_wb2[NG * 9 *  64 * 128];
__device__ __align__(1024) __nv_bfloat16 g_wb3[NG * 9 *  32 *  64];
__device__ __align__(1024) __nv_bfloat16 g_wb4[NG * 9 *  24 *  32];

__device__ __forceinline__ uint32_t smem_u32(const void* p) {
    uint32_t a;
    asm("{ .reg .u64 t; cvta.to.shared.u64 t, %1; cvt.u32.u64 %0, t; }"
        : "=r"(a) : "l"(p));
    return a;
}
__device__ __forceinline__ void cp16(uint32_t dst, const void* src) {
    asm volatile("cp.async.ca.shared.global [%0], [%1], 16;"
                 :: "r"(dst), "l"(src) : "memory");
}
__device__ __forceinline__ uint32_t bf2pack(float lo, float hi) {
    __nv_bfloat162 b = __floats2bfloat162_rn(lo, hi);
    return *reinterpret_cast<uint32_t*>(&b);
}

// ---------------- prep: merged weight reorders + concat/transpose ----------------
// W[g][co][ci][3][3] fp32 -> Wb[g][tap][co(COP)][ci] bf16
template <int CI, int COUT, int COP>
__device__ __forceinline__ void w_reorder_dev(const float* __restrict__ w,
                                              __nv_bfloat16* __restrict__ wr,
                                              int bx, int by, int g, int tid,
                                              __nv_bfloat16 (*s)[8][34]) {
    const int cib = bx * 32, cob = by * 8;
    const int coq = tid >> 5, ci = tid & 31;
    const int co  = cob + coq;
    if (co < COUT) {
        const float* src = w + (((size_t)g * COUT + co) * CI + cib + ci) * 9;
        #pragma unroll
        for (int t = 0; t < 9; t++) s[t][coq][ci] = __float2bfloat16(src[t]);
    } else {
        #pragma unroll
        for (int t = 0; t < 9; t++) s[t][coq][ci] = __float2bfloat16(0.f);
    }
    __syncthreads();
    for (int it = tid; it < 9 * 8 * 16; it += 256) {
        int row = it >> 4, wq = it & 15;
        int tap = row >> 3, col = row & 7;
        uint32_t v = (uint32_t)__bfloat16_as_ushort(s[tap][col][2 * wq]) |
                     ((uint32_t)__bfloat16_as_ushort(s[tap][col][2 * wq + 1]) << 16);
        uint32_t* dst = (uint32_t*)(wr + (((size_t)(g * 9 + tap) * COP) + cob + col) * CI + cib);
        dst[wq] = v;
    }
}

__global__ __launch_bounds__(256)
void prep_kernel(const float* __restrict__ gar, const float* __restrict__ cond,
                 const float* __restrict__ W1, const float* __restrict__ W2,
                 const float* __restrict__ W3, const float* __restrict__ W4,
                 __nv_bfloat16* __restrict__ wb1, __nv_bfloat16* __restrict__ wb2,
                 __nv_bfloat16* __restrict__ wb3, __nv_bfloat16* __restrict__ wb4) {
    __shared__ __nv_bfloat16 sw[9][8][34];
    __shared__ float tf[32][33];
    const int b = blockIdx.x, tid = threadIdx.x;
    if (b < 2048) {                       // L1: 16 x 16 x 8
        w_reorder_dev<512, 128, 128>(W1, wb1, b & 15, (b >> 4) & 15, b >> 8, tid, sw);
    } else if (b < 2304) {                // L2: 4 x 8 x 8
        int r = b - 2048;
        w_reorder_dev<128, 64, 64>(W2, wb2, r & 3, (r >> 2) & 7, r >> 5, tid, sw);
    } else if (b < 2368) {                // L3: 2 x 4 x 8
        int r = b - 2304;
        w_reorder_dev<64, 32, 32>(W3, wb3, r & 1, (r >> 1) & 3, r >> 3, tid, sw);
    } else if (b < 2392) {                // L4: 1 x 3 x 8
        int r = b - 2368;
        w_reorder_dev<32, 18, 24>(W4, wb4, 0, r % 3, r / 3, tid, sw);
    } else {                              // concat/transpose: 128 px-blocks x 16 c-blocks
        int r = b - 2392;
        int bx = r & 127, cy = r >> 7;
        int lx = tid & 31, ly = tid >> 5;
        int p  = bx * 32 + lx;
        int c0 = cy * 32;
        const float* src = (c0 < 256) ? gar + (size_t)c0 * NPIX
                                      : cond + (size_t)(c0 - 256) * NPIX;
        #pragma unroll
        for (int j = 0; j < 32; j += 8)
            tf[ly + j][lx] = src[(size_t)(ly + j) * NPIX + p];
        __syncthreads();
        int p2 = bx * 32 + ly;
        int c  = c0 + lx;
        #pragma unroll
        for (int j = 0; j < 32; j += 8) {
            float v = tf[lx][ly + j];
            g_bin[(size_t)(p2 + j) * 512 + c] = __float2bfloat16(v);
            if (c0 < 256) g_garf[(size_t)(p2 + j) * 256 + c] = v;
        }
    }
}

// ---------------- bf16 mma.sync implicit-GEMM 3x3 conv ---------------------------
template <int CI, int COUT, int COP, int COTILE, int WPX,
          bool RELU, bool OUT_HWC, bool GRP_IN, bool IN_BF16>
__global__ __launch_bounds__(256, 2)
void gemm_conv(const void* __restrict__ inp, const __nv_bfloat16* __restrict__ wr,
               const float* __restrict__ bias, void* __restrict__ outp) {
    constexpr int WCO    = 8 / WPX;
    constexpr int WarpPx = 128 / WPX;
    constexpr int MT     = WarpPx / 16;
    constexpr int WarpCo = COTILE / WCO;
    constexpr int NT     = WarpCo / 8;
    constexpr int NCC    = CI / 32;
    constexpr int NTOT   = NCC * 9;
    constexpr int AW     = 264 * 20;           // words per A buffer
    constexpr int BW     = COTILE * 20;        // words per B buffer

    extern __shared__ uint32_t smu[];
    uint32_t* sA = smu;            // [2][AW]
    uint32_t* sB = smu + 2 * AW;   // [2][BW]

    const int tid = threadIdx.x, lane = tid & 31, wid = tid >> 5;
    const int g   = blockIdx.z;
    const int cob = blockIdx.y * COTILE;
    const int r0  = blockIdx.x * 2;
    const int p0  = blockIdx.x * 128;

    const float*         inf = (const float*)inp         + (GRP_IN ? (size_t)g * NPIX * CI : 0);
    const __nv_bfloat16* ing = (const __nv_bfloat16*)inp + (GRP_IN ? (size_t)g * NPIX * CI : 0);
    const __nv_bfloat16* wb  = wr + (size_t)g * 9 * COP * CI;

    const int wco = wid % WCO, wpx = wid / WCO;
    const int r4  = lane >> 2, l4 = lane & 3;
    const uint32_t sBu = smem_u32(sB);

    // ---- prologue: stage halo chunk 0 + B iter 0 ----
    if constexpr (IN_BF16) {
        for (int it = tid; it < 264 * 4; it += 256) {
            int pos = it >> 2, cf = it & 3;
            int hr = pos / 66, hc = pos - hr * 66;
            int y = r0 - 1 + hr, x = hc - 1;
            uint4 v = make_uint4(0, 0, 0, 0);
            if ((unsigned)y < 64u && (unsigned)x < 64u)
                v = *(const uint4*)(ing + (size_t)(y * HW + x) * CI + cf * 8);
            *(uint4*)(sA + pos * 20 + cf * 4) = v;
        }
    } else {
        for (int it = tid; it < 264 * 8; it += 256) {
            int pos = it >> 3, cf = it & 7;
            int hr = pos / 66, hc = pos - hr * 66;
            int y = r0 - 1 + hr, x = hc - 1;
            float4 v = make_float4(0.f, 0.f, 0.f, 0.f);
            if ((unsigned)y < 64u && (unsigned)x < 64u)
                v = *(const float4*)(inf + (size_t)(y * HW + x) * CI + cf * 4);
            uint32_t* d = sA + pos * 20 + cf * 2;
            d[0] = bf2pack(v.x, v.y);
            d[1] = bf2pack(v.z, v.w);
        }
    }
    for (int it = tid; it < COTILE * 4; it += 256) {
        int co = it >> 2, cf = it & 3;
        uint4 v = *(const uint4*)(wb + (size_t)(cob + co) * CI + cf * 8);
        *(uint4*)(sB + co * 20 + cf * 4) = v;
    }
    __syncthreads();

    float acc[MT][NT][4];
    #pragma unroll
    for (int mt = 0; mt < MT; mt++)
        #pragma unroll
        for (int nt = 0; nt < NT; nt++)
            #pragma unroll
            for (int q = 0; q < 4; q++) acc[mt][nt][q] = 0.f;

    for (int c = 0; c < NTOT; c++) {
        const int cc = c / 9, tap = c - cc * 9;
        const int c1 = c + 1;

        // -- async-prefetch B(c+1) into the other buffer --
        if (c1 < NTOT) {
            int cc2 = c1 / 9, tap2 = c1 - cc2 * 9;
            const __nv_bfloat16* bsrc = wb + (size_t)tap2 * COP * CI + cc2 * 32;
            uint32_t dstb = sBu + (uint32_t)((c1 & 1) * BW) * 4u;
            for (int it = tid; it < COTILE * 4; it += 256) {
                int co = it >> 2, cf = it & 3;
                cp16(dstb + (uint32_t)(co * 20 + cf * 4) * 4u,
                     bsrc + (size_t)(cob + co) * CI + cf * 8);
            }
        }
        asm volatile("cp.async.commit_group;" ::: "memory");

        // -- prefetch A slice 'tap' of chunk cc+1 --
        float4 argf = make_float4(0.f, 0.f, 0.f, 0.f);
        uint4  argb = make_uint4(0, 0, 0, 0);
        int apos = -1, acf = 0;
        if (cc + 1 < NCC) {
            if constexpr (IN_BF16) {
                if (tid < 120) {
                    int pos = tap * 30 + (tid >> 2);
                    if (pos < 264) {
                        apos = pos; acf = tid & 3;
                        int hr = pos / 66, hc = pos - hr * 66;
                        int y = r0 - 1 + hr, x = hc - 1;
                        if ((unsigned)y < 64u && (unsigned)x < 64u)
                            argb = *(const uint4*)(ing + (size_t)(y * HW + x) * CI
                                                   + (cc + 1) * 32 + acf * 8);
                    }
                }
            } else {
                if (tid < 240) {
                    int pos = tap * 30 + (tid >> 3);
                    if (pos < 264) {
                        apos = pos; acf = tid & 7;
                        int hr = pos / 66, hc = pos - hr * 66;
                        int y = r0 - 1 + hr, x = hc - 1;
                        if ((unsigned)y < 64u && (unsigned)x < 64u)
                            argf = *(const float4*)(inf + (size_t)(y * HW + x) * CI
                                                    + (cc + 1) * 32 + acf * 4);
                    }
                }
            }
        }

        // -- compute current (cc, tap) --
        const uint32_t* uA = sA + (cc & 1) * AW;
        const uint32_t* uB = sB + (c  & 1) * BW;
        const int dy = tap / 3, dx = tap - dy * 3;
        const int dtap = (dy * 66 + dx) * 20;
        int abase[MT], bbase[NT];
        #pragma unroll
        for (int mt = 0; mt < MT; mt++) {
            int pb = wpx * WarpPx + mt * 16;
            abase[mt] = dtap + ((pb >> 6) * 66 + (pb & 63) + r4) * 20 + l4;
        }
        #pragma unroll
        for (int nt = 0; nt < NT; nt++)
            bbase[nt] = (wco * WarpCo + nt * 8 + r4) * 20 + l4;

        #pragma unroll
        for (int ks = 0; ks < 2; ks++) {
            const int k8 = ks * 8;
            uint32_t af[MT][4], bf[NT][2];
            #pragma unroll
            for (int mt = 0; mt < MT; mt++) {
                int a0 = abase[mt] + k8;
                af[mt][0] = uA[a0];
                af[mt][1] = uA[a0 + 160];
                af[mt][2] = uA[a0 + 4];
                af[mt][3] = uA[a0 + 164];
            }
            #pragma unroll
            for (int nt = 0; nt < NT; nt++) {
                int b0 = bbase[nt] + k8;
                bf[nt][0] = uB[b0];
                bf[nt][1] = uB[b0 + 4];
            }
            #pragma unroll
            for (int mt = 0; mt < MT; mt++)
                #pragma unroll
                for (int nt = 0; nt < NT; nt++)
                    asm volatile(
                        "mma.sync.aligned.m16n8k16.row.col.f32.bf16.bf16.f32 "
                        "{%0,%1,%2,%3}, {%4,%5,%6,%7}, {%8,%9}, {%0,%1,%2,%3};"
                        : "+f"(acc[mt][nt][0]), "+f"(acc[mt][nt][1]),
                          "+f"(acc[mt][nt][2]), "+f"(acc[mt][nt][3])
                        : "r"(af[mt][0]), "r"(af[mt][1]), "r"(af[mt][2]), "r"(af[mt][3]),
                          "r"(bf[nt][0]), "r"(bf[nt][1]));
        }

        // -- commit prefetched A slice --
        if (apos >= 0) {
            uint32_t* d = sA + ((cc + 1) & 1) * AW + apos * 20;
            if constexpr (IN_BF16) {
                *(uint4*)(d + acf * 4) = argb;
            } else {
                d[acf * 2]     = bf2pack(argf.x, argf.y);
                d[acf * 2 + 1] = bf2pack(argf.z, argf.w);
            }
        }
        asm volatile("cp.async.wait_group 0;" ::: "memory");
        __syncthreads();
    }

    // ---- epilogue: bias + leaky-ReLU + store ----
    #pragma unroll
    for (int mt = 0; mt < MT; mt++) {
        int pxl = wpx * WarpPx + mt * 16 + r4;
        #pragma unroll
        for (int nt = 0; nt < NT; nt++) {
            int co = cob + wco * WarpCo + nt * 8 + 2 * l4;
            float v0 = acc[mt][nt][0], v1 = acc[mt][nt][1];
            float v2 = acc[mt][nt][2], v3 = acc[mt][nt][3];
            if (OUT_HWC) {
                float b0 = bias[g * COUT + co], b1 = bias[g * COUT + co + 1];
                v0 += b0; v1 += b1; v2 += b0; v3 += b1;
                if (RELU) {
                    v0 = (v0 >= 0.f) ? v0 : 0.1f * v0;
                    v1 = (v1 >= 0.f) ? v1 : 0.1f * v1;
                    v2 = (v2 >= 0.f) ? v2 : 0.1f * v2;
                    v3 = (v3 >= 0.f) ? v3 : 0.1f * v3;
                }
                __nv_bfloat16* ob = (__nv_bfloat16*)outp + (size_t)g * NPIX * COUT;
                *(uint32_t*)(ob + (size_t)(p0 + pxl) * COUT + co)     = bf2pack(v0, v1);
                *(uint32_t*)(ob + (size_t)(p0 + pxl + 8) * COUT + co) = bf2pack(v2, v3);
            } else {
                #pragma unroll
                for (int s = 0; s < 2; s++) {
                    int c2 = co + s;
                    if (c2 < COUT) {
                        float bv = bias[g * COUT + c2];
                        float va = (s ? v1 : v0) + bv;
                        float vb = (s ? v3 : v2) + bv;
                        if (RELU) {
                            va = (va >= 0.f) ? va : 0.1f * va;
                            vb = (vb >= 0.f) ? vb : 0.1f * vb;
                        }
                        float* ob = (float*)outp + ((size_t)g * COUT + c2) * NPIX + p0;
                        ob[pxl]     = va;
                        ob[pxl + 8] = vb;
                    }
                }
            }
        }
    }
}

// ---------------- pass A: softmax attention + sample coords --------------------
__global__ void passA_kernel() {
    int idx = blockIdx.x * blockDim.x + threadIdx.x;
    if (idx >= NK * NPIX) return;
    int p = idx & (NPIX - 1);
    int k = idx >> 12;
    int jx = p & 63, jy = p >> 6;

    float a[NG]; float mx = -1e30f;
    #pragma unroll
    for (int g = 0; g < NG; g++) {
        a[g] = g_oa[(size_t)(g * 18 + 12 + k) * NPIX + p];
        mx = fmaxf(mx, a[g]);
    }
    float s = 0.f;
    #pragma unroll
    for (int g = 0; g < NG; g++) { a[g] = __expf(a[g] - mx); s += a[g]; }
    float inv = 1.f / s;
    const float sc = 64.f / 63.f;
    #pragma unroll
    for (int g = 0; g < NG; g++) {
        int sidx = (g * NK + k) * NPIX + p;
        g_at[sidx] = a[g] * inv;
        float ox = g_oa[(size_t)(g * 18 + 2 * k    ) * NPIX + p];
        float oy = g_oa[(size_t)(g * 18 + 2 * k + 1) * NPIX + p];
        g_sx[sidx] = fminf(fmaxf((jx + ox) * sc - 0.5f, 0.f), 63.f);
        g_sy[sidx] = fminf(fmaxf((jy + oy) * sc - 0.5f, 0.f), 63.f);
    }
}

// ---------------- pass C: warp-per-pixel gather, channel-major lanes -------------
// Reads compact fp32 gar [NPIX][256] (4MB): halved footprint vs R9.
__global__ __launch_bounds__(256)
void passC_kernel(const float* __restrict__ mask, float* __restrict__ out) {
    const int lane = threadIdx.x & 31, wid = threadIdx.x >> 5;
    const int p  = blockIdx.x * 8 + wid;
    const int c0 = lane * 4;

    float4 acc0 = make_float4(0.f, 0.f, 0.f, 0.f);
    float4 acc1 = make_float4(0.f, 0.f, 0.f, 0.f);

    #pragma unroll 1
    for (int g = 0; g < NG; g++) {
        float4 pa0 = make_float4(0.f, 0.f, 0.f, 0.f);
        float4 pa1 = make_float4(0.f, 0.f, 0.f, 0.f);
        #pragma unroll 2
        for (int k = 0; k < NK; k++) {
            int s = (g * NK + k) * NPIX + p;
            float sx = g_sx[s], sy = g_sy[s], a = g_at[s];
            float x0f = floorf(sx), y0f = floorf(sy);
            int x0 = (int)x0f, y0 = (int)y0f;
            float wx = sx - x0f, wy = sy - y0f;
            int x1 = min(x0 + 1, 63), y1 = min(y0 + 1, 63);
            float w00 = a * (1.f - wy) * (1.f - wx);
            float w01 = a * (1.f - wy) * wx;
            float w10 = a * wy * (1.f - wx);
            float w11 = a * wy * wx;
            const float* r00 = g_garf + (size_t)(y0 * HW + x0) * 256 + c0;
            const float* r01 = g_garf + (size_t)(y0 * HW + x1) * 256 + c0;
            const float* r10 = g_garf + (size_t)(y1 * HW + x0) * 256 + c0;
            const float* r11 = g_garf + (size_t)(y1 * HW + x1) * 256 + c0;
            float4 a00 = *(const float4*)(r00);
            float4 a01 = *(const float4*)(r01);
            float4 a10 = *(const float4*)(r10);
            float4 a11 = *(const float4*)(r11);
            pa0.x += w00 * a00.x + w01 * a01.x + w10 * a10.x + w11 * a11.x;
            pa0.y += w00 * a00.y + w01 * a01.y + w10 * a10.y + w11 * a11.y;
            pa0.z += w00 * a00.z + w01 * a01.z + w10 * a10.z + w11 * a11.z;
            pa0.w += w00 * a00.w + w01 * a01.w + w10 * a10.w + w11 * a11.w;
            float4 b00 = *(const float4*)(r00 + 128);
            float4 b01 = *(const float4*)(r01 + 128);
            float4 b10 = *(const float4*)(r10 + 128);
            float4 b11 = *(const float4*)(r11 + 128);
            pa1.x += w00 * b00.x + w01 * b01.x + w10 * b10.x + w11 * b11.x;
            pa1.y += w00 * b00.y + w01 * b01.y + w10 * b10.y + w11 * b11.y;
            pa1.z += w00 * b00.z + w01 * b01.z + w10 * b10.z + w11 * b11.z;
            pa1.w += w00 * b00.w + w01 * b01.w + w10 * b10.w + w11 * b11.w;
        }
        const float4 m0 = *(const float4*)(mask + g * 256 + c0);
        const float4 m1 = *(const float4*)(mask + g * 256 + 128 + c0);
        acc0.x += m0.x * pa0.x; acc0.y += m0.y * pa0.y;
        acc0.z += m0.z * pa0.z; acc0.w += m0.w * pa0.w;
        acc1.x += m1.x * pa1.x; acc1.y += m1.y * pa1.y;
        acc1.z += m1.z * pa1.z; acc1.w += m1.w * pa1.w;
    }
    out[(size_t)(c0 + 0) * NPIX + p] = acc0.x;
    out[(size_t)(c0 + 1) * NPIX + p] = acc0.y;
    out[(size_t)(c0 + 2) * NPIX + p] = acc0.z;
    out[(size_t)(c0 + 3) * NPIX + p] = acc0.w;
    out[(size_t)(128 + c0 + 0) * NPIX + p] = acc1.x;
    out[(size_t)(128 + c0 + 1) * NPIX + p] = acc1.y;
    out[(size_t)(128 + c0 + 2) * NPIX + p] = acc1.z;
    out[(size_t)(128 + c0 + 3) * NPIX + p] = acc1.w;
}

// ---------------- host launcher -------------------------------------------------
static void* sym_addr(const void* symbol) {
    void* p = nullptr;
    cudaGetSymbolAddress(&p, symbol);
    return p;
}

static constexpr int smem_bytes(int cotile) {
    return (2 * 264 * 20 + 2 * cotile * 20) * 4;
}

extern "C" void kernel_launch(void* const* d_in, const int* in_sizes, int n_in,
                              void* d_out, int out_size) {
    const float* gar  = (const float*)d_in[0];
    const float* cond = (const float*)d_in[1];
    const float* mask = (const float*)d_in[2];
    const float* W1 = (const float*)d_in[3];
    const float* b1 = (const float*)d_in[4];
    const float* W2 = (const float*)d_in[5];
    const float* b2 = (const float*)d_in[6];
    const float* W3 = (const float*)d_in[7];
    const float* b3 = (const float*)d_in[8];
    const float* W4 = (const float*)d_in[9];
    const float* b4 = (const float*)d_in[10];
    float* out = (float*)d_out;

    void* p_bin = sym_addr(g_bin);
    void* p_b1 = sym_addr(g_b1);
    void* p_b2 = sym_addr(g_b2);
    void* p_b3 = sym_addr(g_b3);
    void* p_oa = sym_addr(g_oa);
    __nv_bfloat16* p_wb1 = (__nv_bfloat16*)sym_addr(g_wb1);
    __nv_bfloat16* p_wb2 = (__nv_bfloat16*)sym_addr(g_wb2);
    __nv_bfloat16* p_wb3 = (__nv_bfloat16*)sym_addr(g_wb3);
    __nv_bfloat16* p_wb4 = (__nv_bfloat16*)sym_addr(g_wb4);

    auto k1 = gemm_conv<512, 128, 128, 128, 4, true,  true,  false, true>;
    auto k2 = gemm_conv<128,  64,  64,  64, 4, true,  true,  true,  true>;
    auto k3 = gemm_conv< 64,  32,  32,  32, 4, true,  true,  true,  true>;
    auto k4 = gemm_conv< 32,  18,  24,  24, 8, false, false, true,  true>;
    cudaFuncSetAttribute(k1, cudaFuncAttributeMaxDynamicSharedMemorySize, smem_bytes(128));
    cudaFuncSetAttribute(k2, cudaFuncAttributeMaxDynamicSharedMemorySize, smem_bytes(64));
    cudaFuncSetAttribute(k3, cudaFuncAttributeMaxDynamicSharedMemorySize, smem_bytes(32));
    cudaFuncSetAttribute(k4, cudaFuncAttributeMaxDynamicSharedMemorySize, smem_bytes(24));

    // merged reorders (blocks 0..2391) + concat/transpose (blocks 2392..4439)
    prep_kernel<<<4440, 256>>>(gar, cond, W1, W2, W3, W4, p_wb1, p_wb2, p_wb3, p_wb4);

    k1<<<dim3(32, 1, NG), 256, smem_bytes(128)>>>(p_bin, p_wb1, b1, p_b1);
    k2<<<dim3(32, 1, NG), 256, smem_bytes(64)>>>(p_b1,  p_wb2, b2, p_b2);
    k3<<<dim3(32, 1, NG), 256, smem_bytes(32)>>>(p_b2,  p_wb3, b3, p_b3);
    k4<<<dim3(32, 1, NG), 256, smem_bytes(24)>>>(p_b3,  p_wb4, b4, p_oa);

    passA_kernel<<<(NK * NPIX + 255) / 256, 256>>>();
    passC_kernel<<<512, 256>>>(mask, out);
}

// round 17
// speedup vs baseline: 7.2540x; 1.0015x over previous
#include <cuda_runtime.h>
#include <cuda_bf16.h>
#include <cstdint>
#include <cstddef>

#define HW    64
#define NPIX  4096
#define NG    8
#define NK    6

// ---------------- scratch (device globals; no allocation anywhere) -------------
__device__ __align__(1024) __nv_bfloat16 g_bin[NPIX * 512];      // concat input bf16 HWC
__device__ __align__(1024) float g_garf[NPIX * 256];             // gar fp32 HWC (passC)
__device__ __align__(1024) __nv_bfloat16 g_b1[NG * NPIX * 128];  // activations bf16 HWC
__device__ __align__(1024) __nv_bfloat16 g_b2[NG * NPIX *  64];
__device__ __align__(1024) __nv_bfloat16 g_b3[NG * NPIX *  32];
__device__ __align__(1024) float g_oa [NG * 18 * NPIX];          // conv4 out NCHW fp32
__device__ __align__(16)   float g_sx [NG * NK * NPIX];
__device__ __align__(16)   float g_sy [NG * NK * NPIX];
__device__ __align__(16)   float g_at [NG * NK * NPIX];
__device__ __align__(1024) __nv_bfloat16 g_wb1[NG * 9 * 128 * 512];  // [g][tap][co][ci]
__device__ __align__(1024) __nv_bfloat16 g_wb2[NG * 9 *  64 * 128];
__device__ __align__(1024) __nv_bfloat16 g_wb3[NG * 9 *  32 *  64];
__device__ __align__(1024) __nv_bfloat16 g_wb4[NG * 9 *  24 *  32];

__device__ __forceinline__ uint32_t smem_u32(const void* p) {
    uint32_t a;
    asm("{ .reg .u64 t; cvta.to.shared.u64 t, %1; cvt.u32.u64 %0, t; }"
        : "=r"(a) : "l"(p));
    return a;
}
__device__ __forceinline__ void cp16(uint32_t dst, const void* src) {
    asm volatile("cp.async.ca.shared.global [%0], [%1], 16;"
                 :: "r"(dst), "l"(src) : "memory");
}
__device__ __forceinline__ uint32_t bf2pack(float lo, float hi) {
    __nv_bfloat162 b = __floats2bfloat162_rn(lo, hi);
    return *reinterpret_cast<uint32_t*>(&b);
}

// ---------------- prep: merged weight reorders + concat/transpose ----------------
// W[g][co][ci][3][3] fp32 -> Wb[g][tap][co(COP)][ci] bf16
template <int CI, int COUT, int COP>
__device__ __forceinline__ void w_reorder_dev(const float* __restrict__ w,
                                              __nv_bfloat16* __restrict__ wr,
                                              int bx, int by, int g, int tid,
                                              __nv_bfloat16 (*s)[8][34]) {
    const int cib = bx * 32, cob = by * 8;
    const int coq = tid >> 5, ci = tid & 31;
    const int co  = cob + coq;
    if (co < COUT) {
        const float* src = w + (((size_t)g * COUT + co) * CI + cib + ci) * 9;
        #pragma unroll
        for (int t = 0; t < 9; t++) s[t][coq][ci] = __float2bfloat16(src[t]);
    } else {
        #pragma unroll
        for (int t = 0; t < 9; t++) s[t][coq][ci] = __float2bfloat16(0.f);
    }
    __syncthreads();
    for (int it = tid; it < 9 * 8 * 16; it += 256) {
        int row = it >> 4, wq = it & 15;
        int tap = row >> 3, col = row & 7;
        uint32_t v = (uint32_t)__bfloat16_as_ushort(s[tap][col][2 * wq]) |
                     ((uint32_t)__bfloat16_as_ushort(s[tap][col][2 * wq + 1]) << 16);
        uint32_t* dst = (uint32_t*)(wr + (((size_t)(g * 9 + tap) * COP) + cob + col) * CI + cib);
        dst[wq] = v;
    }
}

__global__ __launch_bounds__(256)
void prep_kernel(const float* __restrict__ gar, const float* __restrict__ cond,
                 const float* __restrict__ W1, const float* __restrict__ W2,
                 const float* __restrict__ W3, const float* __restrict__ W4,
                 __nv_bfloat16* __restrict__ wb1, __nv_bfloat16* __restrict__ wb2,
                 __nv_bfloat16* __restrict__ wb3, __nv_bfloat16* __restrict__ wb4) {
    __shared__ __nv_bfloat16 sw[9][8][34];
    __shared__ float tf[32][33];
    const int b = blockIdx.x, tid = threadIdx.x;
    if (b < 2048) {                       // L1: 16 x 16 x 8
        w_reorder_dev<512, 128, 128>(W1, wb1, b & 15, (b >> 4) & 15, b >> 8, tid, sw);
    } else if (b < 2304) {                // L2: 4 x 8 x 8
        int r = b - 2048;
        w_reorder_dev<128, 64, 64>(W2, wb2, r & 3, (r >> 2) & 7, r >> 5, tid, sw);
    } else if (b < 2368) {                // L3: 2 x 4 x 8
        int r = b - 2304;
        w_reorder_dev<64, 32, 32>(W3, wb3, r & 1, (r >> 1) & 3, r >> 3, tid, sw);
    } else if (b < 2392) {                // L4: 1 x 3 x 8
        int r = b - 2368;
        w_reorder_dev<32, 18, 24>(W4, wb4, 0, r % 3, r / 3, tid, sw);
    } else {                              // concat/transpose: 128 px-blocks x 16 c-blocks
        int r = b - 2392;
        int bx = r & 127, cy = r >> 7;
        int lx = tid & 31, ly = tid >> 5;
        int p  = bx * 32 + lx;
        int c0 = cy * 32;
        const float* src = (c0 < 256) ? gar + (size_t)c0 * NPIX
                                      : cond + (size_t)(c0 - 256) * NPIX;
        #pragma unroll
        for (int j = 0; j < 32; j += 8)
            tf[ly + j][lx] = src[(size_t)(ly + j) * NPIX + p];
        __syncthreads();
        int p2 = bx * 32 + ly;
        int c  = c0 + lx;
        #pragma unroll
        for (int j = 0; j < 32; j += 8) {
            float v = tf[lx][ly + j];
            g_bin[(size_t)(p2 + j) * 512 + c] = __float2bfloat16(v);
            if (c0 < 256) g_garf[(size_t)(p2 + j) * 256 + c] = v;
        }
    }
}

// ---------------- bf16 mma.sync implicit-GEMM 3x3 conv (chunk-sync version) ------
// Per 32-ci chunk: B for ALL 9 taps staged via cp.async (double-buffered), A halo
// staged once (single buffer, register-relayed across chunks). 9 taps x 2 k-slices
// of MMAs run with no syncs inside a chunk.
template <int CI, int COUT, int COP, int COTILE, int WPX, int OCC,
          bool RELU, bool OUT_HWC, bool GRP_IN>
__global__ __launch_bounds__(256, OCC)
void gemm_conv(const __nv_bfloat16* __restrict__ inp,
               const __nv_bfloat16* __restrict__ wr,
               const float* __restrict__ bias, void* __restrict__ outp) {
    constexpr int WCO    = 8 / WPX;
    constexpr int WarpPx = 128 / WPX;
    constexpr int MT     = WarpPx / 16;
    constexpr int WarpCo = COTILE / WCO;
    constexpr int NT     = WarpCo / 8;
    constexpr int NCC    = CI / 32;
    constexpr int AW     = 264 * 20;           // words, single A buffer
    constexpr int BW     = 9 * COTILE * 20;    // words per B buffer (all 9 taps)

    extern __shared__ uint32_t smu[];
    uint32_t* sA = smu;            // [AW]
    uint32_t* sB = smu + AW;       // [2][BW]

    const int tid = threadIdx.x, lane = tid & 31, wid = tid >> 5;
    const int g   = blockIdx.z;
    const int cob = 0;                         // COTILE == COP for all layers
    const int r0  = blockIdx.x * 2;
    const int p0  = blockIdx.x * 128;

    const __nv_bfloat16* inb = inp + (GRP_IN ? (size_t)g * NPIX * CI : 0);
    const __nv_bfloat16* wb  = wr + (size_t)g * 9 * COP * CI;

    const int wco = wid % WCO, wpx = wid / WCO;
    const int r4  = lane >> 2, l4 = lane & 3;
    const uint32_t sBu = smem_u32(sB);

    // ---- prologue: stage A chunk 0 directly + cp.async B chunk 0 (all taps) ----
    for (int it = tid; it < 264 * 4; it += 256) {
        int pos = it >> 2, seg = it & 3;
        int hr = pos / 66, hc = pos - hr * 66;
        int y = r0 - 1 + hr, x = hc - 1;
        uint4 v = make_uint4(0, 0, 0, 0);
        if ((unsigned)y < 64u && (unsigned)x < 64u)
            v = *(const uint4*)(inb + (size_t)(y * HW + x) * CI + seg * 8);
        *(uint4*)(sA + pos * 20 + seg * 4) = v;
    }
    {
        const __nv_bfloat16* bsrc = wb;        // chunk 0
        for (int it = tid; it < 9 * COTILE * 4; it += 256) {
            int row = it >> 2, seg = it & 3;   // row = tap*COTILE + co
            int tap = row / COTILE, co = row - tap * COTILE;
            cp16(sBu + (uint32_t)(row * 20 + seg * 4) * 4u,
                 bsrc + ((size_t)tap * COP + cob + co) * CI + seg * 8);
        }
    }
    asm volatile("cp.async.commit_group;" ::: "memory");
    asm volatile("cp.async.wait_group 0;" ::: "memory");
    __syncthreads();

    float acc[MT][NT][4];
    #pragma unroll
    for (int mt = 0; mt < MT; mt++)
        #pragma unroll
        for (int nt = 0; nt < NT; nt++)
            #pragma unroll
            for (int q = 0; q < 4; q++) acc[mt][nt][q] = 0.f;

    uint4 areg[5];
    for (int cc = 0; cc < NCC; cc++) {
        const bool more = (cc + 1 < NCC);

        // -- prefetch next chunk: B via cp.async into other buffer, A into regs --
        if (more) {
            const __nv_bfloat16* bsrc = wb + (size_t)(cc + 1) * 32;
            uint32_t dstb = sBu + (uint32_t)(((cc + 1) & 1) * BW) * 4u;
            for (int it = tid; it < 9 * COTILE * 4; it += 256) {
                int row = it >> 2, seg = it & 3;
                int tap = row / COTILE, co = row - tap * COTILE;
                cp16(dstb + (uint32_t)(row * 20 + seg * 4) * 4u,
                     bsrc + ((size_t)tap * COP + cob + co) * CI + seg * 8);
            }
            asm volatile("cp.async.commit_group;" ::: "memory");
            #pragma unroll
            for (int t = 0; t < 5; t++) {
                int it = tid + t * 256;
                areg[t] = make_uint4(0, 0, 0, 0);
                if (it < 1056) {
                    int pos = it >> 2, seg = it & 3;
                    int hr = pos / 66, hc = pos - hr * 66;
                    int y = r0 - 1 + hr, x = hc - 1;
                    if ((unsigned)y < 64u && (unsigned)x < 64u)
                        areg[t] = *(const uint4*)(inb + (size_t)(y * HW + x) * CI
                                                  + (cc + 1) * 32 + seg * 8);
                }
            }
        }

        // -- compute: 9 taps x 2 k-slices, no syncs --
        const uint32_t* uB = sB + (cc & 1) * BW;
        #pragma unroll
        for (int tap = 0; tap < 9; tap++) {
            const int dy = tap / 3, dx = tap - dy * 3;
            const int dtap = (dy * 66 + dx) * 20;
            int abase[MT], bbase[NT];
            #pragma unroll
            for (int mt = 0; mt < MT; mt++) {
                int pb = wpx * WarpPx + mt * 16;
                abase[mt] = dtap + ((pb >> 6) * 66 + (pb & 63) + r4) * 20 + l4;
            }
            #pragma unroll
            for (int nt = 0; nt < NT; nt++)
                bbase[nt] = (tap * COTILE + wco * WarpCo + nt * 8 + r4) * 20 + l4;

            #pragma unroll
            for (int ks = 0; ks < 2; ks++) {
                const int k8 = ks * 8;
                uint32_t af[MT][4], bf[NT][2];
                #pragma unroll
                for (int mt = 0; mt < MT; mt++) {
                    int a0 = abase[mt] + k8;
                    af[mt][0] = sA[a0];
                    af[mt][1] = sA[a0 + 160];
                    af[mt][2] = sA[a0 + 4];
                    af[mt][3] = sA[a0 + 164];
                }
                #pragma unroll
                for (int nt = 0; nt < NT; nt++) {
                    int b0 = bbase[nt] + k8;
                    bf[nt][0] = uB[b0];
                    bf[nt][1] = uB[b0 + 4];
                }
                #pragma unroll
                for (int mt = 0; mt < MT; mt++)
                    #pragma unroll
                    for (int nt = 0; nt < NT; nt++)
                        asm volatile(
                            "mma.sync.aligned.m16n8k16.row.col.f32.bf16.bf16.f32 "
                            "{%0,%1,%2,%3}, {%4,%5,%6,%7}, {%8,%9}, {%0,%1,%2,%3};"
                            : "+f"(acc[mt][nt][0]), "+f"(acc[mt][nt][1]),
                              "+f"(acc[mt][nt][2]), "+f"(acc[mt][nt][3])
                            : "r"(af[mt][0]), "r"(af[mt][1]), "r"(af[mt][2]), "r"(af[mt][3]),
                              "r"(bf[nt][0]), "r"(bf[nt][1]));
            }
        }

        // -- commit A regs to the (single) A buffer; wait B --
        if (more) {
            __syncthreads();                   // all warps done reading sA
            #pragma unroll
            for (int t = 0; t < 5; t++) {
                int it = tid + t * 256;
                if (it < 1056) {
                    int pos = it >> 2, seg = it & 3;
                    *(uint4*)(sA + pos * 20 + seg * 4) = areg[t];
                }
            }
            asm volatile("cp.async.wait_group 0;" ::: "memory");
            __syncthreads();
        }
    }

    // ---- epilogue: bias + leaky-ReLU + store ----
    #pragma unroll
    for (int mt = 0; mt < MT; mt++) {
        int pxl = wpx * WarpPx + mt * 16 + r4;
        #pragma unroll
        for (int nt = 0; nt < NT; nt++) {
            int co = cob + wco * WarpCo + nt * 8 + 2 * l4;
            float v0 = acc[mt][nt][0], v1 = acc[mt][nt][1];
            float v2 = acc[mt][nt][2], v3 = acc[mt][nt][3];
            if (OUT_HWC) {
                float b0 = bias[g * COUT + co], b1 = bias[g * COUT + co + 1];
                v0 += b0; v1 += b1; v2 += b0; v3 += b1;
                if (RELU) {
                    v0 = (v0 >= 0.f) ? v0 : 0.1f * v0;
                    v1 = (v1 >= 0.f) ? v1 : 0.1f * v1;
                    v2 = (v2 >= 0.f) ? v2 : 0.1f * v2;
                    v3 = (v3 >= 0.f) ? v3 : 0.1f * v3;
                }
                __nv_bfloat16* ob = (__nv_bfloat16*)outp + (size_t)g * NPIX * COUT;
                *(uint32_t*)(ob + (size_t)(p0 + pxl) * COUT + co)     = bf2pack(v0, v1);
                *(uint32_t*)(ob + (size_t)(p0 + pxl + 8) * COUT + co) = bf2pack(v2, v3);
            } else {
                #pragma unroll
                for (int s = 0; s < 2; s++) {
                    int c2 = co + s;
                    if (c2 < COUT) {
                        float bv = bias[g * COUT + c2];
                        float va = (s ? v1 : v0) + bv;
                        float vb = (s ? v3 : v2) + bv;
                        if (RELU) {
                            va = (va >= 0.f) ? va : 0.1f * va;
                            vb = (vb >= 0.f) ? vb : 0.1f * vb;
                        }
                        float* ob = (float*)outp + ((size_t)g * COUT + c2) * NPIX + p0;
                        ob[pxl]     = va;
                        ob[pxl + 8] = vb;
                    }
                }
            }
        }
    }
}

// ---------------- pass A: softmax attention + sample coords --------------------
__global__ void passA_kernel() {
    int idx = blockIdx.x * blockDim.x + threadIdx.x;
    if (idx >= NK * NPIX) return;
    int p = idx & (NPIX - 1);
    int k = idx >> 12;
    int jx = p & 63, jy = p >> 6;

    float a[NG]; float mx = -1e30f;
    #pragma unroll
    for (int g = 0; g < NG; g++) {
        a[g] = g_oa[(size_t)(g * 18 + 12 + k) * NPIX + p];
        mx = fmaxf(mx, a[g]);
    }
    float s = 0.f;
    #pragma unroll
    for (int g = 0; g < NG; g++) { a[g] = __expf(a[g] - mx); s += a[g]; }
    float inv = 1.f / s;
    const float sc = 64.f / 63.f;
    #pragma unroll
    for (int g = 0; g < NG; g++) {
        int sidx = (g * NK + k) * NPIX + p;
        g_at[sidx] = a[g] * inv;
        float ox = g_oa[(size_t)(g * 18 + 2 * k    ) * NPIX + p];
        float oy = g_oa[(size_t)(g * 18 + 2 * k + 1) * NPIX + p];
        g_sx[sidx] = fminf(fmaxf((jx + ox) * sc - 0.5f, 0.f), 63.f);
        g_sy[sidx] = fminf(fmaxf((jy + oy) * sc - 0.5f, 0.f), 63.f);
    }
}

// ---------------- pass C: warp-per-pixel gather, channel-major lanes -------------
__global__ __launch_bounds__(256)
void passC_kernel(const float* __restrict__ mask, float* __restrict__ out) {
    const int lane = threadIdx.x & 31, wid = threadIdx.x >> 5;
    const int p  = blockIdx.x * 8 + wid;
    const int c0 = lane * 4;

    float4 acc0 = make_float4(0.f, 0.f, 0.f, 0.f);
    float4 acc1 = make_float4(0.f, 0.f, 0.f, 0.f);

    #pragma unroll 1
    for (int g = 0; g < NG; g++) {
        float4 pa0 = make_float4(0.f, 0.f, 0.f, 0.f);
        float4 pa1 = make_float4(0.f, 0.f, 0.f, 0.f);
        #pragma unroll 2
        for (int k = 0; k < NK; k++) {
            int s = (g * NK + k) * NPIX + p;
            float sx = g_sx[s], sy = g_sy[s], a = g_at[s];
            float x0f = floorf(sx), y0f = floorf(sy);
            int x0 = (int)x0f, y0 = (int)y0f;
            float wx = sx - x0f, wy = sy - y0f;
            int x1 = min(x0 + 1, 63), y1 = min(y0 + 1, 63);
            float w00 = a * (1.f - wy) * (1.f - wx);
            float w01 = a * (1.f - wy) * wx;
            float w10 = a * wy * (1.f - wx);
            float w11 = a * wy * wx;
            const float* r00 = g_garf + (size_t)(y0 * HW + x0) * 256 + c0;
            const float* r01 = g_garf + (size_t)(y0 * HW + x1) * 256 + c0;
            const float* r10 = g_garf + (size_t)(y1 * HW + x0) * 256 + c0;
            const float* r11 = g_garf + (size_t)(y1 * HW + x1) * 256 + c0;
            float4 a00 = *(const float4*)(r00);
            float4 a01 = *(const float4*)(r01);
            float4 a10 = *(const float4*)(r10);
            float4 a11 = *(const float4*)(r11);
            pa0.x += w00 * a00.x + w01 * a01.x + w10 * a10.x + w11 * a11.x;
            pa0.y += w00 * a00.y + w01 * a01.y + w10 * a10.y + w11 * a11.y;
            pa0.z += w00 * a00.z + w01 * a01.z + w10 * a10.z + w11 * a11.z;
            pa0.w += w00 * a00.w + w01 * a01.w + w10 * a10.w + w11 * a11.w;
            float4 b00 = *(const float4*)(r00 + 128);
            float4 b01 = *(const float4*)(r01 + 128);
            float4 b10 = *(const float4*)(r10 + 128);
            float4 b11 = *(const float4*)(r11 + 128);
            pa1.x += w00 * b00.x + w01 * b01.x + w10 * b10.x + w11 * b11.x;
            pa1.y += w00 * b00.y + w01 * b01.y + w10 * b10.y + w11 * b11.y;
            pa1.z += w00 * b00.z + w01 * b01.z + w10 * b10.z + w11 * b11.z;
            pa1.w += w00 * b00.w + w01 * b01.w + w10 * b10.w + w11 * b11.w;
        }
        const float4 m0 = *(const float4*)(mask + g * 256 + c0);
        const float4 m1 = *(const float4*)(mask + g * 256 + 128 + c0);
        acc0.x += m0.x * pa0.x; acc0.y += m0.y * pa0.y;
        acc0.z += m0.z * pa0.z; acc0.w += m0.w * pa0.w;
        acc1.x += m1.x * pa1.x; acc1.y += m1.y * pa1.y;
        acc1.z += m1.z * pa1.z; acc1.w += m1.w * pa1.w;
    }
    out[(size_t)(c0 + 0) * NPIX + p] = acc0.x;
    out[(size_t)(c0 + 1) * NPIX + p] = acc0.y;
    out[(size_t)(c0 + 2) * NPIX + p] = acc0.z;
    out[(size_t)(c0 + 3) * NPIX + p] = acc0.w;
    out[(size_t)(128 + c0 + 0) * NPIX + p] = acc1.x;
    out[(size_t)(128 + c0 + 1) * NPIX + p] = acc1.y;
    out[(size_t)(128 + c0 + 2) * NPIX + p] = acc1.z;
    out[(size_t)(128 + c0 + 3) * NPIX + p] = acc1.w;
}

// ---------------- host launcher -------------------------------------------------
static void* sym_addr(const void* symbol) {
    void* p = nullptr;
    cudaGetSymbolAddress(&p, symbol);
    return p;
}

static constexpr int smem_bytes(int cotile) {
    return (264 * 20 + 2 * 9 * cotile * 20) * 4;
}

extern "C" void kernel_launch(void* const* d_in, const int* in_sizes, int n_in,
                              void* d_out, int out_size) {
    const float* gar  = (const float*)d_in[0];
    const float* cond = (const float*)d_in[1];
    const float* mask = (const float*)d_in[2];
    const float* W1 = (const float*)d_in[3];
    const float* b1 = (const float*)d_in[4];
    const float* W2 = (const float*)d_in[5];
    const float* b2 = (const float*)d_in[6];
    const float* W3 = (const float*)d_in[7];
    const float* b3 = (const float*)d_in[8];
    const float* W4 = (const float*)d_in[9];
    const float* b4 = (const float*)d_in[10];
    float* out = (float*)d_out;

    const __nv_bfloat16* p_bin = (const __nv_bfloat16*)sym_addr(g_bin);
    __nv_bfloat16* p_b1 = (__nv_bfloat16*)sym_addr(g_b1);
    __nv_bfloat16* p_b2 = (__nv_bfloat16*)sym_addr(g_b2);
    __nv_bfloat16* p_b3 = (__nv_bfloat16*)sym_addr(g_b3);
    void* p_oa = sym_addr(g_oa);
    __nv_bfloat16* p_wb1 = (__nv_bfloat16*)sym_addr(g_wb1);
    __nv_bfloat16* p_wb2 = (__nv_bfloat16*)sym_addr(g_wb2);
    __nv_bfloat16* p_wb3 = (__nv_bfloat16*)sym_addr(g_wb3);
    __nv_bfloat16* p_wb4 = (__nv_bfloat16*)sym_addr(g_wb4);

    auto k1 = gemm_conv<512, 128, 128, 128, 4, 1, true,  true,  false>;
    auto k2 = gemm_conv<128,  64,  64,  64, 4, 2, true,  true,  true >;
    auto k3 = gemm_conv< 64,  32,  32,  32, 4, 2, true,  true,  true >;
    auto k4 = gemm_conv< 32,  18,  24,  24, 8, 2, false, false, true >;
    cudaFuncSetAttribute(k1, cudaFuncAttributeMaxDynamicSharedMemorySize, smem_bytes(128));
    cudaFuncSetAttribute(k2, cudaFuncAttributeMaxDynamicSharedMemorySize, smem_bytes(64));
    cudaFuncSetAttribute(k3, cudaFuncAttributeMaxDynamicSharedMemorySize, smem_bytes(32));
    cudaFuncSetAttribute(k4, cudaFuncAttributeMaxDynamicSharedMemorySize, smem_bytes(24));

    // merged reorders (blocks 0..2391) + concat/transpose (blocks 2392..4439)
    prep_kernel<<<4440, 256>>>(gar, cond, W1, W2, W3, W4, p_wb1, p_wb2, p_wb3, p_wb4);

    k1<<<dim3(32, 1, NG), 256, smem_bytes(128)>>>(p_bin, p_wb1, b1, p_b1);
    k2<<<dim3(32, 1, NG), 256, smem_bytes(64)>>>(p_b1,  p_wb2, b2, p_b2);
    k3<<<dim3(32, 1, NG), 256, smem_bytes(32)>>>(p_b2,  p_wb3, b3, p_b3);
    k4<<<dim3(32, 1, NG), 256, smem_bytes(24)>>>(p_b3,  p_wb4, b4, p_oa);

    passA_kernel<<<(NK * NPIX + 255) / 256, 256>>>();
    passC_kernel<<<512, 256>>>(mask, out);
}